// round 4
// baseline (speedup 1.0000x reference)
#include <cuda_runtime.h>
#include <cuda_bf16.h>
#include <math.h>

#define NN 50000
#define EE 800000
#define MT64 ((NN + 63) / 64)
#define NSZ (NN * 64)
#define NBLK_STATS 200
#define SCAN_B ((NN + 127) / 128)
#define TS 4352              // 64*68 floats per smem tile
#define STEP_SMEM (6 * TS * 4)

typedef unsigned long long u64;

// ---------------- f32x2 packed helpers (FFMA2 path, sm_103a) ----------------
__device__ __forceinline__ u64 pk2(float x, float y) {
    u64 r; asm("mov.b64 %0, {%1, %2};" : "=l"(r) : "f"(x), "f"(y)); return r;
}
__device__ __forceinline__ void upk2(u64 v, float& x, float& y) {
    asm("mov.b64 {%0, %1}, %2;" : "=f"(x), "=f"(y) : "l"(v));
}
__device__ __forceinline__ u64 fma2(u64 a, u64 b, u64 c) {
    u64 d; asm("fma.rn.f32x2 %0, %1, %2, %3;" : "=l"(d) : "l"(a), "l"(b), "l"(c)); return d;
}

// ---------------- device scratch (no runtime allocation) ----------------
__device__ float g_stem[(size_t)NN * 192];
__device__ float g_x0[(size_t)NN * 64];
__device__ float g_a[(size_t)NN * 64];
__device__ float g_b[(size_t)NN * 64];
__device__ float g_cell0[(size_t)NN * 256];
__device__ float g_cell1[(size_t)NN * 256];
__device__ float g_sum[(size_t)5 * NSZ];
__device__ float g_nrm[(size_t)5 * NSZ];
__device__ float g_wcat[28 * 7 * 4096];
__device__ float g_wmix[14 * 8];
__device__ float g_stats[384];
__device__ float g_part[NBLK_STATS * 384];
__device__ float g_invdeg[NN];
__device__ float g_invsqrt[NN];
__device__ float g_ew[EE];
__device__ int g_deg[NN];
__device__ int g_cursor[NN];
__device__ int g_rowptr[NN + 1];
__device__ int g_eid[EE];
__device__ int g_srcs[EE];
__device__ int g_bsum[512];

// ---------------- CSR construction ----------------
__global__ void k_zero2(int* a, int* b) {
    int i = blockIdx.x * blockDim.x + threadIdx.x;
    if (i < NN) { a[i] = 0; b[i] = 0; }
}

__global__ void k_deg(const int* __restrict__ dst, int* __restrict__ deg) {
    int e = blockIdx.x * blockDim.x + threadIdx.x;
    if (e < EE) atomicAdd(&deg[dst[e]], 1);
}

__global__ void k_degfin(const int* __restrict__ deg, float* __restrict__ invdeg,
                         float* __restrict__ invsqrt) {
    int i = blockIdx.x * blockDim.x + threadIdx.x;
    if (i < NN) {
        float d = (float)max(deg[i], 1);
        invdeg[i] = 1.0f / d;
        invsqrt[i] = rsqrtf(d);
    }
}

__global__ void k_scan1(const int* __restrict__ deg, int* __restrict__ rowptr,
                        int* __restrict__ bsum) {
    __shared__ int s[128];
    int b = blockIdx.x, t = threadIdx.x;
    int i = b * 128 + t;
    int v = (i < NN) ? deg[i] : 0;
    s[t] = v;
    __syncthreads();
    for (int off = 1; off < 128; off <<= 1) {
        int u = (t >= off) ? s[t - off] : 0;
        __syncthreads();
        s[t] += u;
        __syncthreads();
    }
    if (i < NN) rowptr[i] = s[t] - v;
    if (t == 127) bsum[b] = s[127];
}

__global__ void k_scan2(int* __restrict__ bsum) {
    __shared__ int s[512];
    int t = threadIdx.x;
    int v = (t < SCAN_B) ? bsum[t] : 0;
    s[t] = v;
    __syncthreads();
    for (int off = 1; off < 512; off <<= 1) {
        int u = (t >= off) ? s[t - off] : 0;
        __syncthreads();
        s[t] += u;
        __syncthreads();
    }
    if (t < SCAN_B) bsum[t] = s[t] - v;
}

__global__ void k_scan3(int* __restrict__ rowptr, const int* __restrict__ bsum) {
    int i = blockIdx.x * blockDim.x + threadIdx.x;
    if (i < NN) rowptr[i] += bsum[i >> 7];
    if (i == 0) rowptr[NN] = EE;
}

__global__ void k_scatter(const int* __restrict__ dst, const int* __restrict__ rowptr,
                          int* __restrict__ cursor, int* __restrict__ eid) {
    int e = blockIdx.x * blockDim.x + threadIdx.x;
    if (e < EE) {
        int d = dst[e];
        int pos = rowptr[d] + atomicAdd(&cursor[d], 1);
        eid[pos] = e;
    }
}

__global__ void k_sortfill(const int* __restrict__ rowptr, int* __restrict__ eid,
                           const int* __restrict__ src, const float* __restrict__ invsqrt,
                           int* __restrict__ srcs, float* __restrict__ ew) {
    int n = blockIdx.x * blockDim.x + threadIdx.x;
    if (n >= NN) return;
    int r0 = rowptr[n], r1 = rowptr[n + 1];
    for (int i = r0 + 1; i < r1; i++) {  // insertion sort by edge id -> determinism
        int key = eid[i];
        int j = i - 1;
        while (j >= r0 && eid[j] > key) { eid[j + 1] = eid[j]; j--; }
        eid[j + 1] = key;
    }
    float isd = invsqrt[n];
    for (int p = r0; p < r1; p++) {
        int e = eid[p];
        int s = src[e];
        srcs[p] = s;
        ew[p] = invsqrt[s] * isd;
    }
}

// ---------------- softmax + weight baking ----------------
__global__ void k_softmax(const float* __restrict__ alphas, float* __restrict__ wmix) {
    int r = threadIdx.x;
    if (r >= 14) return;
    float m = -1e30f;
    for (int o = 0; o < 8; o++) m = fmaxf(m, alphas[r * 8 + o]);
    float e[8], s = 0.f;
    for (int o = 0; o < 8; o++) { e[o] = expf(alphas[r * 8 + o] - m); s += e[o]; }
    float inv = 1.0f / s;
    for (int o = 0; o < 8; o++) wmix[r * 8 + o] = e[o] * inv;
}

__global__ void k_bake(const float* __restrict__ wmix,
                       const float* __restrict__ Wgcn, const float* __restrict__ Wss,
                       const float* __restrict__ Wsn, const float* __restrict__ Wgin,
                       const float* __restrict__ Wgc1, const float* __restrict__ Wgc2,
                       const float* __restrict__ Wmlp, const float* __restrict__ Wgcnii,
                       float* __restrict__ wcat) {
    int s = blockIdx.x;          // 0..27  (ci*14+ej)
    int ej = s % 14;
    const float* wv = wmix + ej * 8;
    size_t o = (size_t)s * 4096;
    size_t ob = (size_t)s * 7 * 4096;
    float w1 = wv[1], w2 = wv[2], w3 = wv[3], w4 = wv[4], w5 = wv[5], w6 = wv[6], w7 = wv[7];
    for (int idx = threadIdx.x; idx < 4096; idx += blockDim.x) {
        int kk = idx >> 6, nn = idx & 63;
        float p0 = w3 * Wss[o + idx] + w5 * (Wgc1[o + idx] - Wgc2[o + idx]);
        if (kk == nn) p0 += w1;                       // skip_connect folded into panel0
        wcat[ob + 0 * 4096 + idx] = p0;
        wcat[ob + 1 * 4096 + idx] = w3 * Wsn[o + idx];
        wcat[ob + 2 * 4096 + idx] = w5 * Wgc2[o + idx];
        wcat[ob + 3 * 4096 + idx] = w2 * Wgcn[o + idx];
        wcat[ob + 4 * 4096 + idx] = w4 * Wgin[o + idx];
        wcat[ob + 5 * 4096 + idx] = w6 * Wmlp[o + idx];
        wcat[ob + 6 * 4096 + idx] = w7 * Wgcnii[o + idx];
    }
}

// ---------------- generic tiled GEMM (pre/stem), f32x2 inner ----------------
__global__ __launch_bounds__(256) void k_gemm(const float* __restrict__ A, int lda,
                                              const float* __restrict__ B, int ldb,
                                              float* __restrict__ C, int K) {
    __shared__ float As[TS];
    __shared__ float Bs[TS];
    const int tid = threadIdx.x;
    const int m0 = blockIdx.x * 64;
    const int n0b = blockIdx.y * 64;
    const int tx = tid & 15, ty = tid >> 4;
    const int n0 = tx * 4, mm0 = ty * 4;
    u64 acc[8];
#pragma unroll
    for (int i = 0; i < 8; i++) acc[i] = 0ull;
    for (int kt = 0; kt < K; kt += 64) {
        __syncthreads();
#pragma unroll
        for (int i = 0; i < 16; i++) {
            int idx = tid + i * 256;
            int m = idx >> 6, k = idx & 63;
            int gm = m0 + m;
            As[k * 68 + m] = (gm < NN) ? A[(size_t)gm * lda + kt + k] : 0.f;
            Bs[(idx >> 6) * 68 + (idx & 63)] = B[(size_t)(kt + (idx >> 6)) * ldb + n0b + (idx & 63)];
        }
        __syncthreads();
#pragma unroll 16
        for (int k = 0; k < 64; k++) {
            double2 a01 = *(const double2*)&As[k * 68 + mm0];
            float4 b4 = *(const float4*)&Bs[k * 68 + n0];
            u64 a0 = __double_as_longlong(a01.x);
            u64 a1 = __double_as_longlong(a01.y);
            u64 bx = pk2(b4.x, b4.x), by = pk2(b4.y, b4.y);
            u64 bz = pk2(b4.z, b4.z), bw = pk2(b4.w, b4.w);
            acc[0] = fma2(a0, bx, acc[0]); acc[1] = fma2(a0, by, acc[1]);
            acc[2] = fma2(a0, bz, acc[2]); acc[3] = fma2(a0, bw, acc[3]);
            acc[4] = fma2(a1, bx, acc[4]); acc[5] = fma2(a1, by, acc[5]);
            acc[6] = fma2(a1, bz, acc[6]); acc[7] = fma2(a1, bw, acc[7]);
        }
    }
    float cv[16];
#pragma unroll
    for (int p = 0; p < 2; p++)
#pragma unroll
        for (int c = 0; c < 4; c++) {
            float lo, hi;
            upk2(acc[p * 4 + c], lo, hi);
            cv[(2 * p) * 4 + c] = lo;
            cv[(2 * p + 1) * 4 + c] = hi;
        }
#pragma unroll
    for (int r = 0; r < 4; r++) {
        int gm = m0 + mm0 + r;
        if (gm < NN) {
            float4 c4 = make_float4(cv[r * 4 + 0], cv[r * 4 + 1], cv[r * 4 + 2], cv[r * 4 + 3]);
            *(float4*)&C[(size_t)gm * ldb + n0b + n0] = c4;
        }
    }
}

// ---------------- batchnorm ----------------
__global__ void k_colstats(const float* __restrict__ A, int ncols, float* __restrict__ part) {
    int blk = blockIdx.x;
    int c = threadIdx.x;  // 192
    int rows_per = (NN + NBLK_STATS - 1) / NBLK_STATS;
    int r0 = blk * rows_per;
    int r1 = min(NN, r0 + rows_per);
    float s = 0.f, s2 = 0.f;
    if (c < ncols)
        for (int r = r0; r < r1; r++) {
            float v = A[(size_t)r * ncols + c];
            s += v; s2 += v * v;
        }
    part[blk * 384 + c] = s;
    part[blk * 384 + 192 + c] = s2;
}

__global__ void k_colfin(const float* __restrict__ part, int ncols, float* __restrict__ stats) {
    int c = threadIdx.x;
    if (c >= ncols) return;
    float s = 0.f, s2 = 0.f;
    for (int b = 0; b < NBLK_STATS; b++) { s += part[b * 384 + c]; s2 += part[b * 384 + 192 + c]; }
    float m = s / (float)NN;
    float v = s2 / (float)NN - m * m;
    stats[c] = m;
    stats[192 + c] = rsqrtf(v + 1e-5f);
}

__global__ void k_bnapply(float* __restrict__ A, int ncols, const float* __restrict__ stats,
                          int dorelu) {
    size_t idx = (size_t)blockIdx.x * blockDim.x + threadIdx.x;
    size_t total = (size_t)NN * ncols;
    if (idx >= total) return;
    int c = (int)(idx % ncols);
    float v = (A[idx] - stats[c]) * stats[192 + c];
    if (dorelu) v = fmaxf(v, 0.f);
    A[idx] = v;
}

// ---------------- edge aggregation: one warp per node ----------------
__global__ void k_agg(const float* __restrict__ h, int ldh, const int* __restrict__ rowptr,
                      const int* __restrict__ srcs, const float* __restrict__ ew,
                      float* __restrict__ osum, float* __restrict__ onrm) {
    int warp = (blockIdx.x * blockDim.x + threadIdx.x) >> 5;
    if (warp >= NN) return;
    int lane = threadIdx.x & 31;
    int r0 = rowptr[warp], r1 = rowptr[warp + 1];
    float2 s = make_float2(0.f, 0.f), nrm = make_float2(0.f, 0.f);
    for (int p = r0; p < r1; p++) {
        int si = srcs[p];
        float w = ew[p];
        float2 v = *(const float2*)&h[(size_t)si * ldh + lane * 2];
        s.x += v.x; s.y += v.y;
        nrm.x += w * v.x; nrm.y += w * v.y;
    }
    *(float2*)&osum[(size_t)warp * 64 + lane * 2] = s;
    *(float2*)&onrm[(size_t)warp * 64 + lane * 2] = nrm;
}

// ---------------- fused step kernel: all slots of one step, f32x2 8x4 microtile ----------------
__constant__ int c_psrc[7]  = {0, 1, 2, 3, 2, 0, 4};
__constant__ int c_prelu[7] = {0, 0, 0, 1, 1, 1, 1};

__global__ __launch_bounds__(128, 2) void k_step(
    const float* __restrict__ h0, const float* __restrict__ h1, const float* __restrict__ h2,
    const float* __restrict__ h3, const float* __restrict__ h4,
    int l0, int l1, int l2, int l3, int l4,
    const float* __restrict__ sums, const float* __restrict__ nrms,
    const float* __restrict__ x0, const float* __restrict__ invdeg,
    const float* __restrict__ wbase, int nst, float* __restrict__ outp) {
    extern __shared__ float sm[];
    float* Bs = sm + 5 * TS;
    const int tid = threadIdx.x;
    const int m0 = blockIdx.x * 64;
    const int tx = tid & 15, ty = tid >> 4;
    const int n0 = tx * 4, mm0 = ty * 8;

    float outv[32];
#pragma unroll
    for (int i = 0; i < 32; i++) outv[i] = 0.f;

    // prefetch B panel 0 of slot 0
    float4 Breg[8];
    {
        const float4* W4 = (const float4*)wbase;
#pragma unroll
        for (int i = 0; i < 8; i++) Breg[i] = W4[i * 128 + tid];
    }

    for (int j = 0; j < nst; j++) {
        const float* h = (j == 0) ? h0 : (j == 1) ? h1 : (j == 2) ? h2 : (j == 3) ? h3 : h4;
        int ldh = (j == 0) ? l0 : (j == 1) ? l1 : (j == 2) ? l2 : (j == 3) ? l3 : l4;
        const float* ssum = sums + (size_t)j * NSZ;
        const float* snrm = nrms + (size_t)j * NSZ;
        const float* Wslot = wbase + (size_t)j * 7 * 4096;

        __syncthreads();  // previous slot's panels done reading A
        // build 5 A tiles in [k][m] layout, stride 68
#pragma unroll
        for (int i = 0; i < 32; i++) {
            int idx = tid + i * 128;
            int m = idx >> 6, k = idx & 63;
            int gm = m0 + m;
            float hv = 0.f, sv = 0.f, nv = 0.f, xv = 0.f, idg = 0.f;
            if (gm < NN) {
                hv = h[(size_t)gm * ldh + k];
                sv = ssum[(size_t)gm * 64 + k];
                nv = snrm[(size_t)gm * 64 + k];
                xv = x0[(size_t)gm * 64 + k];
                idg = invdeg[gm];
            }
            int a = k * 68 + m;
            sm[0 * TS + a] = hv;                       // Ah
            sm[1 * TS + a] = sv * idg;                 // Amean
            sm[2 * TS + a] = hv + sv;                  // Ahs
            sm[3 * TS + a] = nv;                       // Anorm
            sm[4 * TS + a] = 0.9f * nv + 0.1f * xv;    // Agmix
        }

        for (int p = 0; p < 7; p++) {
            __syncthreads();  // Bs free (prev panel done reading); A ready (p==0)
#pragma unroll
            for (int i = 0; i < 8; i++) {
                int idx = (i * 128 + tid) * 4;
                *(float4*)&Bs[(idx >> 6) * 68 + (idx & 63)] = Breg[i];
            }
            __syncthreads();
            // prefetch next panel (or next slot's panel 0)
            const float* wp = 0;
            if (p < 6) wp = Wslot + (size_t)(p + 1) * 4096;
            else if (j + 1 < nst) wp = Wslot + (size_t)7 * 4096;
            if (wp) {
                const float4* W4 = (const float4*)wp;
#pragma unroll
                for (int i = 0; i < 8; i++) Breg[i] = W4[i * 128 + tid];
            }
            const float* As = sm + c_psrc[p] * TS;
            u64 acc[16];
#pragma unroll
            for (int i = 0; i < 16; i++) acc[i] = 0ull;
#pragma unroll 8
            for (int k = 0; k < 64; k++) {
                double2 a01 = *(const double2*)&As[k * 68 + mm0];
                double2 a23 = *(const double2*)&As[k * 68 + mm0 + 4];
                float4 b4 = *(const float4*)&Bs[k * 68 + n0];
                u64 a0 = __double_as_longlong(a01.x);
                u64 a1 = __double_as_longlong(a01.y);
                u64 a2 = __double_as_longlong(a23.x);
                u64 a3 = __double_as_longlong(a23.y);
                u64 bx = pk2(b4.x, b4.x), by = pk2(b4.y, b4.y);
                u64 bz = pk2(b4.z, b4.z), bw = pk2(b4.w, b4.w);
                acc[0]  = fma2(a0, bx, acc[0]);  acc[1]  = fma2(a0, by, acc[1]);
                acc[2]  = fma2(a0, bz, acc[2]);  acc[3]  = fma2(a0, bw, acc[3]);
                acc[4]  = fma2(a1, bx, acc[4]);  acc[5]  = fma2(a1, by, acc[5]);
                acc[6]  = fma2(a1, bz, acc[6]);  acc[7]  = fma2(a1, bw, acc[7]);
                acc[8]  = fma2(a2, bx, acc[8]);  acc[9]  = fma2(a2, by, acc[9]);
                acc[10] = fma2(a2, bz, acc[10]); acc[11] = fma2(a2, bw, acc[11]);
                acc[12] = fma2(a3, bx, acc[12]); acc[13] = fma2(a3, by, acc[13]);
                acc[14] = fma2(a3, bz, acc[14]); acc[15] = fma2(a3, bw, acc[15]);
            }
            if (c_prelu[p]) {
#pragma unroll
                for (int q = 0; q < 4; q++)
#pragma unroll
                    for (int c = 0; c < 4; c++) {
                        float lo, hi;
                        upk2(acc[q * 4 + c], lo, hi);
                        outv[(2 * q) * 4 + c] += fmaxf(lo, 0.f);
                        outv[(2 * q + 1) * 4 + c] += fmaxf(hi, 0.f);
                    }
            } else {
#pragma unroll
                for (int q = 0; q < 4; q++)
#pragma unroll
                    for (int c = 0; c < 4; c++) {
                        float lo, hi;
                        upk2(acc[q * 4 + c], lo, hi);
                        outv[(2 * q) * 4 + c] += lo;
                        outv[(2 * q + 1) * 4 + c] += hi;
                    }
            }
        }
    }
    // single write of the new state
#pragma unroll
    for (int r = 0; r < 8; r++) {
        int gm = m0 + mm0 + r;
        if (gm < NN) {
            float4 c4 = make_float4(outv[r * 4 + 0], outv[r * 4 + 1], outv[r * 4 + 2], outv[r * 4 + 3]);
            *(float4*)&outp[(size_t)gm * 256 + n0] = c4;
        }
    }
}

// ---------------- classifier ----------------
__global__ void k_cls(const float* __restrict__ s1, const float* __restrict__ W,
                      const float* __restrict__ b, float* __restrict__ out) {
    int n = blockIdx.x;
    __shared__ float row[256];
    __shared__ float red[64];
    int tid = threadIdx.x;  // 64
    float ls = 0.f;
#pragma unroll
    for (int i = 0; i < 4; i++) {
        float v = s1[(size_t)n * 256 + tid + i * 64];
        row[tid + i * 64] = v;
        ls += v;
    }
    red[tid] = ls;
    __syncthreads();
    for (int off = 32; off > 0; off >>= 1) {
        if (tid < off) red[tid] += red[tid + off];
        __syncthreads();
    }
    float pooled = red[0] * (1.0f / 256.0f);
    if (tid < 40) {
        float acc = b[tid] + pooled * W[tid];
#pragma unroll 8
        for (int k = 0; k < 256; k++) acc += row[k] * W[(1 + k) * 40 + tid];
        out[(size_t)n * 40 + tid] = acc;
    }
}

// ---------------- host orchestration ----------------
static void bnrun(float* buf, int ncols, int dorelu, float* part, float* stats) {
    k_colstats<<<NBLK_STATS, 192>>>(buf, ncols, part);
    k_colfin<<<1, 192>>>(part, ncols, stats);
    size_t total = (size_t)NN * ncols;
    k_bnapply<<<(int)((total + 255) / 256), 256>>>(buf, ncols, stats, dorelu);
}

extern "C" void kernel_launch(void* const* d_in, const int* in_sizes, int n_in,
                              void* d_out, int out_size) {
    const float* x = (const float*)d_in[0];
    const int* ei = (const int*)d_in[1];
    const float* alphas = (const float*)d_in[2];
    const float* stemW = (const float*)d_in[3];
    const float* preW = (const float*)d_in[4];
    const float* p0W0 = (const float*)d_in[5];
    const float* p1W0 = (const float*)d_in[6];
    const float* p0W1 = (const float*)d_in[7];
    const float* p1W1 = (const float*)d_in[8];
    const float* Wgcn = (const float*)d_in[9];
    const float* Wss = (const float*)d_in[10];
    const float* Wsn = (const float*)d_in[11];
    const float* Wgin = (const float*)d_in[12];
    const float* Wgc1 = (const float*)d_in[13];
    const float* Wgc2 = (const float*)d_in[14];
    const float* Wmlp = (const float*)d_in[15];
    const float* Wgcnii = (const float*)d_in[16];
    const float* clsW = (const float*)d_in[17];
    const float* clsb = (const float*)d_in[18];
    float* out = (float*)d_out;
    const int* srcI = ei;
    const int* dstI = ei + EE;

    float *stem, *x0p, *ap, *bp, *c0, *c1, *sums, *nrms, *wcat, *wmix, *stats, *part;
    float *invdeg, *invsqrt, *ew;
    int *deg, *cursor, *rowptr, *eid, *srcs, *bsum;
    cudaGetSymbolAddress((void**)&stem, g_stem);
    cudaGetSymbolAddress((void**)&x0p, g_x0);
    cudaGetSymbolAddress((void**)&ap, g_a);
    cudaGetSymbolAddress((void**)&bp, g_b);
    cudaGetSymbolAddress((void**)&c0, g_cell0);
    cudaGetSymbolAddress((void**)&c1, g_cell1);
    cudaGetSymbolAddress((void**)&sums, g_sum);
    cudaGetSymbolAddress((void**)&nrms, g_nrm);
    cudaGetSymbolAddress((void**)&wcat, g_wcat);
    cudaGetSymbolAddress((void**)&wmix, g_wmix);
    cudaGetSymbolAddress((void**)&stats, g_stats);
    cudaGetSymbolAddress((void**)&part, g_part);
    cudaGetSymbolAddress((void**)&invdeg, g_invdeg);
    cudaGetSymbolAddress((void**)&invsqrt, g_invsqrt);
    cudaGetSymbolAddress((void**)&ew, g_ew);
    cudaGetSymbolAddress((void**)&deg, g_deg);
    cudaGetSymbolAddress((void**)&cursor, g_cursor);
    cudaGetSymbolAddress((void**)&rowptr, g_rowptr);
    cudaGetSymbolAddress((void**)&eid, g_eid);
    cudaGetSymbolAddress((void**)&srcs, g_srcs);
    cudaGetSymbolAddress((void**)&bsum, g_bsum);

    cudaFuncSetAttribute(k_step, cudaFuncAttributeMaxDynamicSharedMemorySize, STEP_SMEM);

    // --- CSR build (deterministic via per-node eid sort) ---
    k_zero2<<<(NN + 255) / 256, 256>>>(deg, cursor);
    k_deg<<<(EE + 255) / 256, 256>>>(dstI, deg);
    k_degfin<<<(NN + 255) / 256, 256>>>(deg, invdeg, invsqrt);
    k_scan1<<<SCAN_B, 128>>>(deg, rowptr, bsum);
    k_scan2<<<1, 512>>>(bsum);
    k_scan3<<<(NN + 255) / 256, 256>>>(rowptr, bsum);
    k_scatter<<<(EE + 255) / 256, 256>>>(dstI, rowptr, cursor, eid);
    k_sortfill<<<(NN + 127) / 128, 128>>>(rowptr, eid, srcI, invsqrt, srcs, ew);

    // --- architecture weights ---
    k_softmax<<<1, 16>>>(alphas, wmix);
    k_bake<<<28, 256>>>(wmix, Wgcn, Wss, Wsn, Wgin, Wgc1, Wgc2, Wmlp, Wgcnii, wcat);

    // --- stem + preprocess ---
    k_gemm<<<dim3(MT64, 3), 256>>>(x, 128, stemW, 192, stem, 128);
    bnrun(stem, 192, 0, part, stats);
    k_gemm<<<dim3(MT64, 1), 256>>>(x, 128, preW, 64, x0p, 128);
    bnrun(x0p, 64, 1, part, stats);

    const int aggBlocks = (NN * 32 + 255) / 256;

    // --- cells ---
    for (int ci = 0; ci < 2; ci++) {
        const float* s0 = stem; int k0 = 192;
        const float* s1 = (ci == 0) ? stem : c0;
        int k1 = (ci == 0) ? 192 : 256;
        const float* pW0 = (ci == 0) ? p0W0 : p0W1;
        const float* pW1 = (ci == 0) ? p1W0 : p1W1;
        float* cell = (ci == 0) ? c0 : c1;

        k_gemm<<<dim3(MT64, 1), 256>>>(s0, k0, pW0, 64, ap, k0);
        bnrun(ap, 64, 1, part, stats);
        k_gemm<<<dim3(MT64, 1), 256>>>(s1, k1, pW1, 64, bp, k1);
        bnrun(bp, 64, 1, part, stats);

        const float* sp[5] = {ap, bp, cell, cell + 64, cell + 128};
        const int sl[5] = {64, 64, 256, 256, 256};

        k_agg<<<aggBlocks, 256>>>(sp[0], sl[0], rowptr, srcs, ew, sums + 0 * (size_t)NSZ, nrms + 0 * (size_t)NSZ);
        k_agg<<<aggBlocks, 256>>>(sp[1], sl[1], rowptr, srcs, ew, sums + 1 * (size_t)NSZ, nrms + 1 * (size_t)NSZ);

        int ej0 = 0;
        for (int t = 0; t < 4; t++) {
            float* outp = cell + t * 64;
            const float* wbase = wcat + (size_t)(ci * 14 + ej0) * 7 * 4096;
            k_step<<<MT64, 128, STEP_SMEM>>>(sp[0], sp[1], sp[2], sp[3], sp[4],
                                             sl[0], sl[1], sl[2], sl[3], sl[4],
                                             sums, nrms, x0p, invdeg, wbase, t + 2, outp);
            ej0 += t + 2;
            if (t < 3) {
                int ns = t + 2;
                k_agg<<<aggBlocks, 256>>>(sp[ns], sl[ns], rowptr, srcs, ew,
                                          sums + (size_t)ns * NSZ, nrms + (size_t)ns * NSZ);
            }
        }
    }

    // --- classifier ---
    k_cls<<<NN, 64>>>(c1, clsW, clsb, out);
}

// round 5
// speedup vs baseline: 1.0124x; 1.0124x over previous
#include <cuda_runtime.h>
#include <cuda_bf16.h>
#include <math.h>

#define NN 50000
#define EE 800000
#define MT64 ((NN + 63) / 64)
#define NSZ (NN * 64)
#define NBLK_STATS 200
#define SCAN_B ((NN + 127) / 128)
#define TS 4352              // 64*68 floats per smem tile
#define STEP_SMEM (6 * TS * 4)

typedef unsigned long long u64;

// ---------------- f32x2 packed helpers (FFMA2 path, sm_103a) ----------------
__device__ __forceinline__ u64 pk2(float x, float y) {
    u64 r; asm("mov.b64 %0, {%1, %2};" : "=l"(r) : "f"(x), "f"(y)); return r;
}
__device__ __forceinline__ void upk2(u64 v, float& x, float& y) {
    asm("mov.b64 {%0, %1}, %2;" : "=f"(x), "=f"(y) : "l"(v));
}
__device__ __forceinline__ u64 fma2(u64 a, u64 b, u64 c) {
    u64 d; asm("fma.rn.f32x2 %0, %1, %2, %3;" : "=l"(d) : "l"(a), "l"(b), "l"(c)); return d;
}

// ---------------- device scratch (no runtime allocation) ----------------
__device__ float g_stem[(size_t)NN * 192];
__device__ float g_x0[(size_t)NN * 64];
__device__ float g_a[(size_t)NN * 64];
__device__ float g_b[(size_t)NN * 64];
__device__ float g_cell0[(size_t)NN * 256];
__device__ float g_cell1[(size_t)NN * 256];
__device__ float g_sum[(size_t)5 * NSZ];
__device__ float g_nrm[(size_t)5 * NSZ];
__device__ float g_wcat[28 * 7 * 4096];
__device__ float g_wmix[14 * 8];
__device__ float g_stats[384];
__device__ float g_part[NBLK_STATS * 384];
__device__ float g_invdeg[NN];
__device__ float g_invsqrt[NN];
__device__ float g_ew[EE];
__device__ int g_deg[NN];
__device__ int g_cursor[NN];
__device__ int g_rowptr[NN + 1];
__device__ int g_eid[EE];
__device__ int g_srcs[EE];
__device__ int g_bsum[512];

// ---------------- CSR construction ----------------
__global__ void k_zero2(int* a, int* b) {
    int i = blockIdx.x * blockDim.x + threadIdx.x;
    if (i < NN) { a[i] = 0; b[i] = 0; }
}

__global__ void k_deg(const int* __restrict__ dst, int* __restrict__ deg) {
    int e = blockIdx.x * blockDim.x + threadIdx.x;
    if (e < EE) atomicAdd(&deg[dst[e]], 1);
}

__global__ void k_degfin(const int* __restrict__ deg, float* __restrict__ invdeg,
                         float* __restrict__ invsqrt) {
    int i = blockIdx.x * blockDim.x + threadIdx.x;
    if (i < NN) {
        float d = (float)max(deg[i], 1);
        invdeg[i] = 1.0f / d;
        invsqrt[i] = rsqrtf(d);
    }
}

__global__ void k_scan1(const int* __restrict__ deg, int* __restrict__ rowptr,
                        int* __restrict__ bsum) {
    __shared__ int s[128];
    int b = blockIdx.x, t = threadIdx.x;
    int i = b * 128 + t;
    int v = (i < NN) ? deg[i] : 0;
    s[t] = v;
    __syncthreads();
    for (int off = 1; off < 128; off <<= 1) {
        int u = (t >= off) ? s[t - off] : 0;
        __syncthreads();
        s[t] += u;
        __syncthreads();
    }
    if (i < NN) rowptr[i] = s[t] - v;
    if (t == 127) bsum[b] = s[127];
}

__global__ void k_scan2(int* __restrict__ bsum) {
    __shared__ int s[512];
    int t = threadIdx.x;
    int v = (t < SCAN_B) ? bsum[t] : 0;
    s[t] = v;
    __syncthreads();
    for (int off = 1; off < 512; off <<= 1) {
        int u = (t >= off) ? s[t - off] : 0;
        __syncthreads();
        s[t] += u;
        __syncthreads();
    }
    if (t < SCAN_B) bsum[t] = s[t] - v;
}

__global__ void k_scan3(int* __restrict__ rowptr, const int* __restrict__ bsum) {
    int i = blockIdx.x * blockDim.x + threadIdx.x;
    if (i < NN) rowptr[i] += bsum[i >> 7];
    if (i == 0) rowptr[NN] = EE;
}

__global__ void k_scatter(const int* __restrict__ dst, const int* __restrict__ rowptr,
                          int* __restrict__ cursor, int* __restrict__ eid) {
    int e = blockIdx.x * blockDim.x + threadIdx.x;
    if (e < EE) {
        int d = dst[e];
        int pos = rowptr[d] + atomicAdd(&cursor[d], 1);
        eid[pos] = e;
    }
}

__global__ void k_sortfill(const int* __restrict__ rowptr, int* __restrict__ eid,
                           const int* __restrict__ src, const float* __restrict__ invsqrt,
                           int* __restrict__ srcs, float* __restrict__ ew) {
    int n = blockIdx.x * blockDim.x + threadIdx.x;
    if (n >= NN) return;
    int r0 = rowptr[n], r1 = rowptr[n + 1];
    for (int i = r0 + 1; i < r1; i++) {  // insertion sort by edge id -> determinism
        int key = eid[i];
        int j = i - 1;
        while (j >= r0 && eid[j] > key) { eid[j + 1] = eid[j]; j--; }
        eid[j + 1] = key;
    }
    float isd = invsqrt[n];
    for (int p = r0; p < r1; p++) {
        int e = eid[p];
        int s = src[e];
        srcs[p] = s;
        ew[p] = invsqrt[s] * isd;
    }
}

// ---------------- softmax + weight baking ----------------
__global__ void k_softmax(const float* __restrict__ alphas, float* __restrict__ wmix) {
    int r = threadIdx.x;
    if (r >= 14) return;
    float m = -1e30f;
    for (int o = 0; o < 8; o++) m = fmaxf(m, alphas[r * 8 + o]);
    float e[8], s = 0.f;
    for (int o = 0; o < 8; o++) { e[o] = expf(alphas[r * 8 + o] - m); s += e[o]; }
    float inv = 1.0f / s;
    for (int o = 0; o < 8; o++) wmix[r * 8 + o] = e[o] * inv;
}

__global__ void k_bake(const float* __restrict__ wmix,
                       const float* __restrict__ Wgcn, const float* __restrict__ Wss,
                       const float* __restrict__ Wsn, const float* __restrict__ Wgin,
                       const float* __restrict__ Wgc1, const float* __restrict__ Wgc2,
                       const float* __restrict__ Wmlp, const float* __restrict__ Wgcnii,
                       float* __restrict__ wcat) {
    int s = blockIdx.x;          // 0..27  (ci*14+ej)
    int ej = s % 14;
    const float* wv = wmix + ej * 8;
    size_t o = (size_t)s * 4096;
    size_t ob = (size_t)s * 7 * 4096;
    float w1 = wv[1], w2 = wv[2], w3 = wv[3], w4 = wv[4], w5 = wv[5], w6 = wv[6], w7 = wv[7];
    for (int idx = threadIdx.x; idx < 4096; idx += blockDim.x) {
        int kk = idx >> 6, nn = idx & 63;
        float p0 = w3 * Wss[o + idx] + w5 * (Wgc1[o + idx] - Wgc2[o + idx]);
        if (kk == nn) p0 += w1;                       // skip_connect folded into panel0
        wcat[ob + 0 * 4096 + idx] = p0;
        wcat[ob + 1 * 4096 + idx] = w3 * Wsn[o + idx];
        wcat[ob + 2 * 4096 + idx] = w5 * Wgc2[o + idx];
        wcat[ob + 3 * 4096 + idx] = w2 * Wgcn[o + idx];
        wcat[ob + 4 * 4096 + idx] = w4 * Wgin[o + idx];
        wcat[ob + 5 * 4096 + idx] = w6 * Wmlp[o + idx];
        wcat[ob + 6 * 4096 + idx] = w7 * Wgcnii[o + idx];
    }
}

// ---------------- generic tiled GEMM (pre/stem), f32x2 inner ----------------
__global__ __launch_bounds__(256) void k_gemm(const float* __restrict__ A, int lda,
                                              const float* __restrict__ B, int ldb,
                                              float* __restrict__ C, int K) {
    __shared__ float As[TS];
    __shared__ float Bs[TS];
    const int tid = threadIdx.x;
    const int m0 = blockIdx.x * 64;
    const int n0b = blockIdx.y * 64;
    const int tx = tid & 15, ty = tid >> 4;
    const int n0 = tx * 4, mm0 = ty * 4;
    u64 acc[8];
#pragma unroll
    for (int i = 0; i < 8; i++) acc[i] = 0ull;
    for (int kt = 0; kt < K; kt += 64) {
        __syncthreads();
#pragma unroll
        for (int i = 0; i < 16; i++) {
            int idx = tid + i * 256;
            int m = idx >> 6, k = idx & 63;
            int gm = m0 + m;
            As[k * 68 + m] = (gm < NN) ? A[(size_t)gm * lda + kt + k] : 0.f;
            Bs[(idx >> 6) * 68 + (idx & 63)] = B[(size_t)(kt + (idx >> 6)) * ldb + n0b + (idx & 63)];
        }
        __syncthreads();
#pragma unroll 16
        for (int k = 0; k < 64; k++) {
            double2 a01 = *(const double2*)&As[k * 68 + mm0];
            float4 b4 = *(const float4*)&Bs[k * 68 + n0];
            u64 a0 = __double_as_longlong(a01.x);
            u64 a1 = __double_as_longlong(a01.y);
            u64 bx = pk2(b4.x, b4.x), by = pk2(b4.y, b4.y);
            u64 bz = pk2(b4.z, b4.z), bw = pk2(b4.w, b4.w);
            acc[0] = fma2(a0, bx, acc[0]); acc[1] = fma2(a0, by, acc[1]);
            acc[2] = fma2(a0, bz, acc[2]); acc[3] = fma2(a0, bw, acc[3]);
            acc[4] = fma2(a1, bx, acc[4]); acc[5] = fma2(a1, by, acc[5]);
            acc[6] = fma2(a1, bz, acc[6]); acc[7] = fma2(a1, bw, acc[7]);
        }
    }
    float cv[16];
#pragma unroll
    for (int p = 0; p < 2; p++)
#pragma unroll
        for (int c = 0; c < 4; c++) {
            float lo, hi;
            upk2(acc[p * 4 + c], lo, hi);
            cv[(2 * p) * 4 + c] = lo;
            cv[(2 * p + 1) * 4 + c] = hi;
        }
#pragma unroll
    for (int r = 0; r < 4; r++) {
        int gm = m0 + mm0 + r;
        if (gm < NN) {
            float4 c4 = make_float4(cv[r * 4 + 0], cv[r * 4 + 1], cv[r * 4 + 2], cv[r * 4 + 3]);
            *(float4*)&C[(size_t)gm * ldb + n0b + n0] = c4;
        }
    }
}

// ---------------- batchnorm ----------------
__global__ void k_colstats(const float* __restrict__ A, int ncols, float* __restrict__ part) {
    int blk = blockIdx.x;
    int c = threadIdx.x;  // 192
    int rows_per = (NN + NBLK_STATS - 1) / NBLK_STATS;
    int r0 = blk * rows_per;
    int r1 = min(NN, r0 + rows_per);
    float s = 0.f, s2 = 0.f;
    if (c < ncols)
        for (int r = r0; r < r1; r++) {
            float v = A[(size_t)r * ncols + c];
            s += v; s2 += v * v;
        }
    part[blk * 384 + c] = s;
    part[blk * 384 + 192 + c] = s2;
}

__global__ void k_colfin(const float* __restrict__ part, int ncols, float* __restrict__ stats) {
    int c = threadIdx.x;
    if (c >= ncols) return;
    float s = 0.f, s2 = 0.f;
    for (int b = 0; b < NBLK_STATS; b++) { s += part[b * 384 + c]; s2 += part[b * 384 + 192 + c]; }
    float m = s / (float)NN;
    float v = s2 / (float)NN - m * m;
    stats[c] = m;
    stats[192 + c] = rsqrtf(v + 1e-5f);
}

__global__ void k_bnapply(float* __restrict__ A, int ncols, const float* __restrict__ stats,
                          int dorelu) {
    size_t idx = (size_t)blockIdx.x * blockDim.x + threadIdx.x;
    size_t total = (size_t)NN * ncols;
    if (idx >= total) return;
    int c = (int)(idx % ncols);
    float v = (A[idx] - stats[c]) * stats[192 + c];
    if (dorelu) v = fmaxf(v, 0.f);
    A[idx] = v;
}

// ---------------- edge aggregation: one warp per node ----------------
__global__ void k_agg(const float* __restrict__ h, int ldh, const int* __restrict__ rowptr,
                      const int* __restrict__ srcs, const float* __restrict__ ew,
                      float* __restrict__ osum, float* __restrict__ onrm) {
    int warp = (blockIdx.x * blockDim.x + threadIdx.x) >> 5;
    if (warp >= NN) return;
    int lane = threadIdx.x & 31;
    int r0 = rowptr[warp], r1 = rowptr[warp + 1];
    float2 s = make_float2(0.f, 0.f), nrm = make_float2(0.f, 0.f);
    for (int p = r0; p < r1; p++) {
        int si = srcs[p];
        float w = ew[p];
        float2 v = *(const float2*)&h[(size_t)si * ldh + lane * 2];
        s.x += v.x; s.y += v.y;
        nrm.x += w * v.x; nrm.y += w * v.y;
    }
    *(float2*)&osum[(size_t)warp * 64 + lane * 2] = s;
    *(float2*)&onrm[(size_t)warp * 64 + lane * 2] = nrm;
}

// ---------------- fused step kernel: all slots of one step, f32x2 8x4 microtile ----------------
__constant__ int c_psrc[7]  = {0, 1, 2, 3, 2, 0, 4};
__constant__ int c_prelu[7] = {0, 0, 0, 1, 1, 1, 1};

__global__ __launch_bounds__(128, 2) void k_step(
    const float* __restrict__ h0, const float* __restrict__ h1, const float* __restrict__ h2,
    const float* __restrict__ h3, const float* __restrict__ h4,
    int l0, int l1, int l2, int l3, int l4,
    const float* __restrict__ sums, const float* __restrict__ nrms,
    const float* __restrict__ x0, const float* __restrict__ invdeg,
    const float* __restrict__ wbase, int nst, float* __restrict__ outp) {
    extern __shared__ float sm[];
    float* Bs = sm + 5 * TS;
    const int tid = threadIdx.x;
    const int m0 = blockIdx.x * 64;
    const int tx = tid & 15, ty = tid >> 4;
    const int n0 = tx * 4, mm0 = ty * 8;

    float outv[32];
#pragma unroll
    for (int i = 0; i < 32; i++) outv[i] = 0.f;

    // prefetch B panel 0 of slot 0
    float4 Breg[8];
    {
        const float4* W4 = (const float4*)wbase;
#pragma unroll
        for (int i = 0; i < 8; i++) Breg[i] = W4[i * 128 + tid];
    }

    for (int j = 0; j < nst; j++) {
        const float* h = (j == 0) ? h0 : (j == 1) ? h1 : (j == 2) ? h2 : (j == 3) ? h3 : h4;
        int ldh = (j == 0) ? l0 : (j == 1) ? l1 : (j == 2) ? l2 : (j == 3) ? l3 : l4;
        const float* ssum = sums + (size_t)j * NSZ;
        const float* snrm = nrms + (size_t)j * NSZ;
        const float* Wslot = wbase + (size_t)j * 7 * 4096;

        __syncthreads();  // previous slot's panels done reading A
        // build 5 A tiles in [k][m] layout, stride 68
#pragma unroll
        for (int i = 0; i < 32; i++) {
            int idx = tid + i * 128;
            int m = idx >> 6, k = idx & 63;
            int gm = m0 + m;
            float hv = 0.f, sv = 0.f, nv = 0.f, xv = 0.f, idg = 0.f;
            if (gm < NN) {
                hv = h[(size_t)gm * ldh + k];
                sv = ssum[(size_t)gm * 64 + k];
                nv = snrm[(size_t)gm * 64 + k];
                xv = x0[(size_t)gm * 64 + k];
                idg = invdeg[gm];
            }
            int a = k * 68 + m;
            sm[0 * TS + a] = hv;                       // Ah
            sm[1 * TS + a] = sv * idg;                 // Amean
            sm[2 * TS + a] = hv + sv;                  // Ahs
            sm[3 * TS + a] = nv;                       // Anorm
            sm[4 * TS + a] = 0.9f * nv + 0.1f * xv;    // Agmix
        }

        for (int p = 0; p < 7; p++) {
            __syncthreads();  // Bs free (prev panel done reading); A ready (p==0)
#pragma unroll
            for (int i = 0; i < 8; i++) {
                int idx = (i * 128 + tid) * 4;
                *(float4*)&Bs[(idx >> 6) * 68 + (idx & 63)] = Breg[i];
            }
            __syncthreads();
            // prefetch next panel (or next slot's panel 0)
            const float* wp = 0;
            if (p < 6) wp = Wslot + (size_t)(p + 1) * 4096;
            else if (j + 1 < nst) wp = Wslot + (size_t)7 * 4096;
            if (wp) {
                const float4* W4 = (const float4*)wp;
#pragma unroll
                for (int i = 0; i < 8; i++) Breg[i] = W4[i * 128 + tid];
            }
            const float* As = sm + c_psrc[p] * TS;
            u64 acc[16];
#pragma unroll
            for (int i = 0; i < 16; i++) acc[i] = 0ull;
#pragma unroll 8
            for (int k = 0; k < 64; k++) {
                double2 a01 = *(const double2*)&As[k * 68 + mm0];
                double2 a23 = *(const double2*)&As[k * 68 + mm0 + 4];
                float4 b4 = *(const float4*)&Bs[k * 68 + n0];
                u64 a0 = __double_as_longlong(a01.x);
                u64 a1 = __double_as_longlong(a01.y);
                u64 a2 = __double_as_longlong(a23.x);
                u64 a3 = __double_as_longlong(a23.y);
                u64 bx = pk2(b4.x, b4.x), by = pk2(b4.y, b4.y);
                u64 bz = pk2(b4.z, b4.z), bw = pk2(b4.w, b4.w);
                acc[0]  = fma2(a0, bx, acc[0]);  acc[1]  = fma2(a0, by, acc[1]);
                acc[2]  = fma2(a0, bz, acc[2]);  acc[3]  = fma2(a0, bw, acc[3]);
                acc[4]  = fma2(a1, bx, acc[4]);  acc[5]  = fma2(a1, by, acc[5]);
                acc[6]  = fma2(a1, bz, acc[6]);  acc[7]  = fma2(a1, bw, acc[7]);
                acc[8]  = fma2(a2, bx, acc[8]);  acc[9]  = fma2(a2, by, acc[9]);
                acc[10] = fma2(a2, bz, acc[10]); acc[11] = fma2(a2, bw, acc[11]);
                acc[12] = fma2(a3, bx, acc[12]); acc[13] = fma2(a3, by, acc[13]);
                acc[14] = fma2(a3, bz, acc[14]); acc[15] = fma2(a3, bw, acc[15]);
            }
            if (c_prelu[p]) {
#pragma unroll
                for (int q = 0; q < 4; q++)
#pragma unroll
                    for (int c = 0; c < 4; c++) {
                        float lo, hi;
                        upk2(acc[q * 4 + c], lo, hi);
                        outv[(2 * q) * 4 + c] += fmaxf(lo, 0.f);
                        outv[(2 * q + 1) * 4 + c] += fmaxf(hi, 0.f);
                    }
            } else {
#pragma unroll
                for (int q = 0; q < 4; q++)
#pragma unroll
                    for (int c = 0; c < 4; c++) {
                        float lo, hi;
                        upk2(acc[q * 4 + c], lo, hi);
                        outv[(2 * q) * 4 + c] += lo;
                        outv[(2 * q + 1) * 4 + c] += hi;
                    }
            }
        }
    }
    // single write of the new state
#pragma unroll
    for (int r = 0; r < 8; r++) {
        int gm = m0 + mm0 + r;
        if (gm < NN) {
            float4 c4 = make_float4(outv[r * 4 + 0], outv[r * 4 + 1], outv[r * 4 + 2], outv[r * 4 + 3]);
            *(float4*)&outp[(size_t)gm * 256 + n0] = c4;
        }
    }
}

// ---------------- classifier ----------------
__global__ void k_cls(const float* __restrict__ s1, const float* __restrict__ W,
                      const float* __restrict__ b, float* __restrict__ out) {
    int n = blockIdx.x;
    __shared__ float row[256];
    __shared__ float red[64];
    int tid = threadIdx.x;  // 64
    float ls = 0.f;
#pragma unroll
    for (int i = 0; i < 4; i++) {
        float v = s1[(size_t)n * 256 + tid + i * 64];
        row[tid + i * 64] = v;
        ls += v;
    }
    red[tid] = ls;
    __syncthreads();
    for (int off = 32; off > 0; off >>= 1) {
        if (tid < off) red[tid] += red[tid + off];
        __syncthreads();
    }
    float pooled = red[0] * (1.0f / 256.0f);
    if (tid < 40) {
        float acc = b[tid] + pooled * W[tid];
#pragma unroll 8
        for (int k = 0; k < 256; k++) acc += row[k] * W[(1 + k) * 40 + tid];
        out[(size_t)n * 40 + tid] = acc;
    }
}

// ---------------- host orchestration ----------------
static void bnrun(float* buf, int ncols, int dorelu, float* part, float* stats) {
    k_colstats<<<NBLK_STATS, 192>>>(buf, ncols, part);
    k_colfin<<<1, 192>>>(part, ncols, stats);
    size_t total = (size_t)NN * ncols;
    k_bnapply<<<(int)((total + 255) / 256), 256>>>(buf, ncols, stats, dorelu);
}

extern "C" void kernel_launch(void* const* d_in, const int* in_sizes, int n_in,
                              void* d_out, int out_size) {
    const float* x = (const float*)d_in[0];
    const int* ei = (const int*)d_in[1];
    const float* alphas = (const float*)d_in[2];
    const float* stemW = (const float*)d_in[3];
    const float* preW = (const float*)d_in[4];
    const float* p0W0 = (const float*)d_in[5];
    const float* p1W0 = (const float*)d_in[6];
    const float* p0W1 = (const float*)d_in[7];
    const float* p1W1 = (const float*)d_in[8];
    const float* Wgcn = (const float*)d_in[9];
    const float* Wss = (const float*)d_in[10];
    const float* Wsn = (const float*)d_in[11];
    const float* Wgin = (const float*)d_in[12];
    const float* Wgc1 = (const float*)d_in[13];
    const float* Wgc2 = (const float*)d_in[14];
    const float* Wmlp = (const float*)d_in[15];
    const float* Wgcnii = (const float*)d_in[16];
    const float* clsW = (const float*)d_in[17];
    const float* clsb = (const float*)d_in[18];
    float* out = (float*)d_out;
    const int* srcI = ei;
    const int* dstI = ei + EE;

    float *stem, *x0p, *ap, *bp, *c0, *c1, *sums, *nrms, *wcat, *wmix, *stats, *part;
    float *invdeg, *invsqrt, *ew;
    int *deg, *cursor, *rowptr, *eid, *srcs, *bsum;
    cudaGetSymbolAddress((void**)&stem, g_stem);
    cudaGetSymbolAddress((void**)&x0p, g_x0);
    cudaGetSymbolAddress((void**)&ap, g_a);
    cudaGetSymbolAddress((void**)&bp, g_b);
    cudaGetSymbolAddress((void**)&c0, g_cell0);
    cudaGetSymbolAddress((void**)&c1, g_cell1);
    cudaGetSymbolAddress((void**)&sums, g_sum);
    cudaGetSymbolAddress((void**)&nrms, g_nrm);
    cudaGetSymbolAddress((void**)&wcat, g_wcat);
    cudaGetSymbolAddress((void**)&wmix, g_wmix);
    cudaGetSymbolAddress((void**)&stats, g_stats);
    cudaGetSymbolAddress((void**)&part, g_part);
    cudaGetSymbolAddress((void**)&invdeg, g_invdeg);
    cudaGetSymbolAddress((void**)&invsqrt, g_invsqrt);
    cudaGetSymbolAddress((void**)&ew, g_ew);
    cudaGetSymbolAddress((void**)&deg, g_deg);
    cudaGetSymbolAddress((void**)&cursor, g_cursor);
    cudaGetSymbolAddress((void**)&rowptr, g_rowptr);
    cudaGetSymbolAddress((void**)&eid, g_eid);
    cudaGetSymbolAddress((void**)&srcs, g_srcs);
    cudaGetSymbolAddress((void**)&bsum, g_bsum);

    cudaFuncSetAttribute(k_step, cudaFuncAttributeMaxDynamicSharedMemorySize, STEP_SMEM);

    // --- CSR build (deterministic via per-node eid sort) ---
    k_zero2<<<(NN + 255) / 256, 256>>>(deg, cursor);
    k_deg<<<(EE + 255) / 256, 256>>>(dstI, deg);
    k_degfin<<<(NN + 255) / 256, 256>>>(deg, invdeg, invsqrt);
    k_scan1<<<SCAN_B, 128>>>(deg, rowptr, bsum);
    k_scan2<<<1, 512>>>(bsum);
    k_scan3<<<(NN + 255) / 256, 256>>>(rowptr, bsum);
    k_scatter<<<(EE + 255) / 256, 256>>>(dstI, rowptr, cursor, eid);
    k_sortfill<<<(NN + 127) / 128, 128>>>(rowptr, eid, srcI, invsqrt, srcs, ew);

    // --- architecture weights ---
    k_softmax<<<1, 16>>>(alphas, wmix);
    k_bake<<<28, 256>>>(wmix, Wgcn, Wss, Wsn, Wgin, Wgc1, Wgc2, Wmlp, Wgcnii, wcat);

    // --- stem + preprocess ---
    k_gemm<<<dim3(MT64, 3), 256>>>(x, 128, stemW, 192, stem, 128);
    bnrun(stem, 192, 0, part, stats);
    k_gemm<<<dim3(MT64, 1), 256>>>(x, 128, preW, 64, x0p, 128);
    bnrun(x0p, 64, 1, part, stats);

    const int aggBlocks = (NN * 32 + 255) / 256;

    // --- cells ---
    for (int ci = 0; ci < 2; ci++) {
        const float* s0 = stem; int k0 = 192;
        const float* s1 = (ci == 0) ? stem : c0;
        int k1 = (ci == 0) ? 192 : 256;
        const float* pW0 = (ci == 0) ? p0W0 : p0W1;
        const float* pW1 = (ci == 0) ? p1W0 : p1W1;
        float* cell = (ci == 0) ? c0 : c1;

        k_gemm<<<dim3(MT64, 1), 256>>>(s0, k0, pW0, 64, ap, k0);
        bnrun(ap, 64, 1, part, stats);
        k_gemm<<<dim3(MT64, 1), 256>>>(s1, k1, pW1, 64, bp, k1);
        bnrun(bp, 64, 1, part, stats);

        const float* sp[5] = {ap, bp, cell, cell + 64, cell + 128};
        const int sl[5] = {64, 64, 256, 256, 256};

        k_agg<<<aggBlocks, 256>>>(sp[0], sl[0], rowptr, srcs, ew, sums + 0 * (size_t)NSZ, nrms + 0 * (size_t)NSZ);
        k_agg<<<aggBlocks, 256>>>(sp[1], sl[1], rowptr, srcs, ew, sums + 1 * (size_t)NSZ, nrms + 1 * (size_t)NSZ);

        int ej0 = 0;
        for (int t = 0; t < 4; t++) {
            float* outp = cell + t * 64;
            const float* wbase = wcat + (size_t)(ci * 14 + ej0) * 7 * 4096;
            k_step<<<MT64, 128, STEP_SMEM>>>(sp[0], sp[1], sp[2], sp[3], sp[4],
                                             sl[0], sl[1], sl[2], sl[3], sl[4],
                                             sums, nrms, x0p, invdeg, wbase, t + 2, outp);
            ej0 += t + 2;
            if (t < 3) {
                int ns = t + 2;
                k_agg<<<aggBlocks, 256>>>(sp[ns], sl[ns], rowptr, srcs, ew,
                                          sums + (size_t)ns * NSZ, nrms + (size_t)ns * NSZ);
            }
        }
    }

    // --- classifier ---
    k_cls<<<NN, 64>>>(c1, clsW, clsb, out);
}

// round 7
// speedup vs baseline: 1.5054x; 1.4870x over previous
#include <cuda_runtime.h>
#include <cuda_bf16.h>
#include <mma.h>
#include <math.h>
using namespace nvcuda;

#define NN 50000
#define EE 800000
#define MT64 ((NN + 63) / 64)
#define MT128 ((NN + 127) / 128)
#define NSZ (NN * 64)
#define NBLK_STATS 200
#define SCAN_B ((NN + 127) / 128)
#define TS 4352
typedef unsigned int u32;

// smem byte offsets for k_step (A stride 72 bf16 = 144B/row, 128 rows = 18432B/tile)
#define AH 0
#define AS 36864
#define AN 73728
#define AX 110592
#define ALO 18432          // lo tile offset relative to hi
#define BHI 147456
#define BLO 156672         // BHI + 64*144
#define CST 165888         // 8 warps x 4352B
#define STEP_SMEM 200704

__device__ __forceinline__ void bsplit(float x, unsigned short& hb, unsigned short& lb) {
    __nv_bfloat16 h = __float2bfloat16_rn(x);
    float r = x - __bfloat162float(h);
    __nv_bfloat16 l = __float2bfloat16_rn(r);
    hb = *(unsigned short*)&h;
    lb = *(unsigned short*)&l;
}
__device__ __forceinline__ void store_split4(char* hp, char* lp, float4 v) {
    unsigned short h0, l0, h1, l1, h2, l2, h3, l3;
    bsplit(v.x, h0, l0); bsplit(v.y, h1, l1); bsplit(v.z, h2, l2); bsplit(v.w, h3, l3);
    *(uint2*)hp = make_uint2(((u32)h1 << 16) | h0, ((u32)h3 << 16) | h2);
    *(uint2*)lp = make_uint2(((u32)l1 << 16) | l0, ((u32)l3 << 16) | l2);
}

__device__ float g_stem[(size_t)NN * 192];
__device__ float g_x0[(size_t)NN * 64];
__device__ float g_a[(size_t)NN * 64];
__device__ float g_b[(size_t)NN * 64];
__device__ float g_cell0[(size_t)NN * 256];
__device__ float g_cell1[(size_t)NN * 256];
__device__ float g_sum[(size_t)5 * NSZ];
__device__ float g_nrm[(size_t)5 * NSZ];
__device__ __nv_bfloat16 g_wbk[(size_t)28 * 7 * 8192];  // per panel: hi[64][64] then lo[64][64]
__device__ float g_wmix[14 * 8];
__device__ float g_stats[384];
__device__ float g_part[NBLK_STATS * 384];
__device__ float g_invdeg[NN];
__device__ float g_invsqrt[NN];
__device__ float g_ew[EE];
__device__ int g_deg[NN];
__device__ int g_cursor[NN];
__device__ int g_rowptr[NN + 1];
__device__ int g_eid[EE];
__device__ int g_srcs[EE];
__device__ int g_bsum[512];

// ---------------- CSR ----------------
__global__ void k_zero2(int* a, int* b) {
    int i = blockIdx.x * blockDim.x + threadIdx.x;
    if (i < NN) { a[i] = 0; b[i] = 0; }
}
__global__ void k_deg(const int* __restrict__ dst, int* __restrict__ deg) {
    int e = blockIdx.x * blockDim.x + threadIdx.x;
    if (e < EE) atomicAdd(&deg[dst[e]], 1);
}
__global__ void k_degfin(const int* __restrict__ deg, float* __restrict__ invdeg,
                         float* __restrict__ invsqrt) {
    int i = blockIdx.x * blockDim.x + threadIdx.x;
    if (i < NN) {
        float d = (float)max(deg[i], 1);
        invdeg[i] = 1.0f / d;
        invsqrt[i] = rsqrtf(d);
    }
}
__global__ void k_scan1(const int* __restrict__ deg, int* __restrict__ rowptr, int* __restrict__ bsum) {
    __shared__ int s[128];
    int b = blockIdx.x, t = threadIdx.x;
    int i = b * 128 + t;
    int v = (i < NN) ? deg[i] : 0;
    s[t] = v;
    __syncthreads();
    for (int off = 1; off < 128; off <<= 1) {
        int u = (t >= off) ? s[t - off] : 0;
        __syncthreads();
        s[t] += u;
        __syncthreads();
    }
    if (i < NN) rowptr[i] = s[t] - v;
    if (t == 127) bsum[b] = s[127];
}
__global__ void k_scan2(int* __restrict__ bsum) {
    __shared__ int s[512];
    int t = threadIdx.x;
    int v = (t < SCAN_B) ? bsum[t] : 0;
    s[t] = v;
    __syncthreads();
    for (int off = 1; off < 512; off <<= 1) {
        int u = (t >= off) ? s[t - off] : 0;
        __syncthreads();
        s[t] += u;
        __syncthreads();
    }
    if (t < SCAN_B) bsum[t] = s[t] - v;
}
__global__ void k_scan3(int* __restrict__ rowptr, const int* __restrict__ bsum) {
    int i = blockIdx.x * blockDim.x + threadIdx.x;
    if (i < NN) rowptr[i] += bsum[i >> 7];
    if (i == 0) rowptr[NN] = EE;
}
__global__ void k_scatter(const int* __restrict__ dst, const int* __restrict__ rowptr,
                          int* __restrict__ cursor, int* __restrict__ eid) {
    int e = blockIdx.x * blockDim.x + threadIdx.x;
    if (e < EE) {
        int d = dst[e];
        int pos = rowptr[d] + atomicAdd(&cursor[d], 1);
        eid[pos] = e;
    }
}
__global__ void k_sortfill(const int* __restrict__ rowptr, int* __restrict__ eid,
                           const int* __restrict__ src, const float* __restrict__ invsqrt,
                           int* __restrict__ srcs, float* __restrict__ ew) {
    int n = blockIdx.x * blockDim.x + threadIdx.x;
    if (n >= NN) return;
    int r0 = rowptr[n], r1 = rowptr[n + 1];
    for (int i = r0 + 1; i < r1; i++) {
        int key = eid[i];
        int j = i - 1;
        while (j >= r0 && eid[j] > key) { eid[j + 1] = eid[j]; j--; }
        eid[j + 1] = key;
    }
    float isd = invsqrt[n];
    for (int p = r0; p < r1; p++) {
        int e = eid[p];
        int s = src[e];
        srcs[p] = s;
        ew[p] = invsqrt[s] * isd;
    }
}
__global__ void k_softmax(const float* __restrict__ alphas, float* __restrict__ wmix) {
    int r = threadIdx.x;
    if (r >= 14) return;
    float m = -1e30f;
    for (int o = 0; o < 8; o++) m = fmaxf(m, alphas[r * 8 + o]);
    float e[8], s = 0.f;
    for (int o = 0; o < 8; o++) { e[o] = expf(alphas[r * 8 + o] - m); s += e[o]; }
    float inv = 1.0f / s;
    for (int o = 0; o < 8; o++) wmix[r * 8 + o] = e[o] * inv;
}

// bake 7 bf16-split B panels per slot. Panel p, [k][n] row-major, hi 4096 then lo 4096 bf16.
__global__ void k_bake(const float* __restrict__ wmix,
                       const float* __restrict__ Wgcn, const float* __restrict__ Wss,
                       const float* __restrict__ Wsn, const float* __restrict__ Wgin,
                       const float* __restrict__ Wgc1, const float* __restrict__ Wgc2,
                       const float* __restrict__ Wmlp, const float* __restrict__ Wgcnii,
                       __nv_bfloat16* __restrict__ wbk) {
    int s = blockIdx.x;
    int ej = s % 14;
    const float* wv = wmix + ej * 8;
    size_t o = (size_t)s * 4096;
    __nv_bfloat16* ob = wbk + (size_t)s * 7 * 8192;
    float w1 = wv[1], w2 = wv[2], w3 = wv[3], w4 = wv[4], w5 = wv[5], w6 = wv[6], w7 = wv[7];
    for (int idx = threadIdx.x; idx < 4096; idx += blockDim.x) {
        int k = idx >> 6, n = idx & 63;
        for (int p = 0; p < 7; p++) {
            float v;
            if (p == 0) v = w3 * Wss[o + idx] + w5 * Wgc1[o + idx] + ((k == n) ? w1 : 0.f);
            else if (p == 1) v = w5 * Wgc2[o + idx];
            else if (p == 2) v = w3 * Wsn[o + idx];
            else if (p == 3) v = w2 * Wgcn[o + idx];
            else if (p == 4) v = w4 * Wgin[o + idx];
            else if (p == 5) v = w6 * Wmlp[o + idx];
            else v = 0.9f * w7 * Wgcnii[o + idx];
            unsigned short hb, lb;
            bsplit(v, hb, lb);
            ob[p * 8192 + idx] = *(__nv_bfloat16*)&hb;
            ob[p * 8192 + 4096 + idx] = *(__nv_bfloat16*)&lb;
        }
    }
}

// ---------------- fp32 tiled GEMM (stem/pre) ----------------
__global__ __launch_bounds__(256) void k_gemm(const float* __restrict__ A, int lda,
                                              const float* __restrict__ B, int ldb,
                                              float* __restrict__ C, int K) {
    __shared__ float As[TS];
    __shared__ float Bs[TS];
    const int tid = threadIdx.x;
    const int m0 = blockIdx.x * 64;
    const int n0b = blockIdx.y * 64;
    const int n0 = (tid & 15) * 4, mm0 = (tid >> 4) * 4;
    float acc[16];
#pragma unroll
    for (int i = 0; i < 16; i++) acc[i] = 0.f;
    for (int kt = 0; kt < K; kt += 64) {
        __syncthreads();
#pragma unroll
        for (int i = 0; i < 16; i++) {
            int idx = tid + i * 256;
            int m = idx >> 6, k = idx & 63;
            int gm = m0 + m;
            As[k * 68 + m] = (gm < NN) ? A[(size_t)gm * lda + kt + k] : 0.f;
            Bs[(idx >> 6) * 68 + (idx & 63)] = B[(size_t)(kt + (idx >> 6)) * ldb + n0b + (idx & 63)];
        }
        __syncthreads();
#pragma unroll 16
        for (int k = 0; k < 64; k++) {
            float4 a4 = *(const float4*)&As[k * 68 + mm0];
            float4 b4 = *(const float4*)&Bs[k * 68 + n0];
            acc[0] += a4.x * b4.x; acc[1] += a4.x * b4.y; acc[2] += a4.x * b4.z; acc[3] += a4.x * b4.w;
            acc[4] += a4.y * b4.x; acc[5] += a4.y * b4.y; acc[6] += a4.y * b4.z; acc[7] += a4.y * b4.w;
            acc[8] += a4.z * b4.x; acc[9] += a4.z * b4.y; acc[10] += a4.z * b4.z; acc[11] += a4.z * b4.w;
            acc[12] += a4.w * b4.x; acc[13] += a4.w * b4.y; acc[14] += a4.w * b4.z; acc[15] += a4.w * b4.w;
        }
    }
#pragma unroll
    for (int r = 0; r < 4; r++) {
        int gm = m0 + mm0 + r;
        if (gm < NN)
            *(float4*)&C[(size_t)gm * ldb + n0b + n0] =
                make_float4(acc[r * 4], acc[r * 4 + 1], acc[r * 4 + 2], acc[r * 4 + 3]);
    }
}

// ---------------- batchnorm ----------------
__global__ void k_colstats(const float* __restrict__ A, int ncols, float* __restrict__ part) {
    int blk = blockIdx.x, c = threadIdx.x;
    int rows_per = (NN + NBLK_STATS - 1) / NBLK_STATS;
    int r0 = blk * rows_per, r1 = min(NN, r0 + rows_per);
    float s = 0.f, s2 = 0.f;
    if (c < ncols)
        for (int r = r0; r < r1; r++) {
            float v = A[(size_t)r * ncols + c];
            s += v; s2 += v * v;
        }
    part[blk * 384 + c] = s;
    part[blk * 384 + 192 + c] = s2;
}
__global__ void k_colfin(const float* __restrict__ part, int ncols, float* __restrict__ stats) {
    int c = threadIdx.x;
    if (c >= ncols) return;
    float s = 0.f, s2 = 0.f;
    for (int b = 0; b < NBLK_STATS; b++) { s += part[b * 384 + c]; s2 += part[b * 384 + 192 + c]; }
    float m = s / (float)NN;
    float v = s2 / (float)NN - m * m;
    stats[c] = m;
    stats[192 + c] = rsqrtf(v + 1e-5f);
}
__global__ void k_bnapply(float* __restrict__ A, int ncols, const float* __restrict__ stats, int dorelu) {
    size_t idx = (size_t)blockIdx.x * blockDim.x + threadIdx.x;
    if (idx >= (size_t)NN * ncols) return;
    int c = (int)(idx % ncols);
    float v = (A[idx] - stats[c]) * stats[192 + c];
    if (dorelu) v = fmaxf(v, 0.f);
    A[idx] = v;
}
__global__ void k_agg(const float* __restrict__ h, int ldh, const int* __restrict__ rowptr,
                      const int* __restrict__ srcs, const float* __restrict__ ew,
                      float* __restrict__ osum, float* __restrict__ onrm) {
    int warp = (blockIdx.x * blockDim.x + threadIdx.x) >> 5;
    if (warp >= NN) return;
    int lane = threadIdx.x & 31;
    int r0 = rowptr[warp], r1 = rowptr[warp + 1];
    float2 s = make_float2(0.f, 0.f), nrm = make_float2(0.f, 0.f);
    for (int p = r0; p < r1; p++) {
        int si = srcs[p];
        float w = ew[p];
        float2 v = *(const float2*)&h[(size_t)si * ldh + lane * 2];
        s.x += v.x; s.y += v.y;
        nrm.x += w * v.x; nrm.y += w * v.y;
    }
    *(float2*)&osum[(size_t)warp * 64 + lane * 2] = s;
    *(float2*)&onrm[(size_t)warp * 64 + lane * 2] = nrm;
}

// ---------------- wmma bf16-split step kernel ----------------
typedef wmma::fragment<wmma::matrix_a, 16, 16, 16, __nv_bfloat16, wmma::row_major> FragA;
typedef wmma::fragment<wmma::matrix_b, 16, 16, 16, __nv_bfloat16, wmma::row_major> FragB;
typedef wmma::fragment<wmma::accumulator, 16, 16, 16, float> FragC;

__device__ __forceinline__ void mma_pass(FragC fc[4], const char* smc, int aoff, int boff, int wrow) {
    FragA fa;
    FragB fb;
#pragma unroll
    for (int kc = 0; kc < 4; kc++) {
        wmma::load_matrix_sync(fa, (const __nv_bfloat16*)(smc + aoff) + wrow * 72 + kc * 16, 72);
#pragma unroll
        for (int nf = 0; nf < 4; nf++) {
            wmma::load_matrix_sync(fb, (const __nv_bfloat16*)(smc + boff) + kc * 16 * 72 + nf * 16, 72);
            wmma::mma_sync(fc[nf], fa, fb, fc[nf]);
        }
    }
}

__global__ __launch_bounds__(256, 1) void k_step(
    const float* __restrict__ h0p, const float* __restrict__ h1p, const float* __restrict__ h2p,
    const float* __restrict__ h3p, const float* __restrict__ h4p,
    int l0, int l1, int l2, int l3, int l4,
    const float* __restrict__ sums, const float* __restrict__ nrms,
    const float* __restrict__ x0, const float* __restrict__ invdeg,
    const __nv_bfloat16* __restrict__ wbase, int nst, float* __restrict__ outp) {
    extern __shared__ char smc[];
    const int tid = threadIdx.x, wid = tid >> 5, lane = tid & 31;
    const int m0 = blockIdx.x * 128;
    const int wrow = wid * 16;
    const int mE = m0 + wrow + (lane >> 1);
    const float idg = (mE < NN) ? invdeg[mE] : 0.f;
    float* cst = (float*)(smc + CST + wid * 4352);

    // x0/9 tile, built once
#pragma unroll
    for (int i = 0; i < 8; i++) {
        int idx = tid + i * 256;
        int row = idx >> 4, cg = (idx & 15) * 4;
        int gm = m0 + row;
        float4 xv = (gm < NN) ? *(const float4*)(x0 + (size_t)gm * 64 + cg)
                              : make_float4(0.f, 0.f, 0.f, 0.f);
        const float s9 = 1.0f / 9.0f;
        xv.x *= s9; xv.y *= s9; xv.z *= s9; xv.w *= s9;
        int off = row * 144 + cg * 2;
        store_split4(smc + AX + off, smc + AX + ALO + off, xv);
    }

    float outv[32];
#pragma unroll
    for (int i = 0; i < 32; i++) outv[i] = 0.f;
    FragC fc[4];

    const int na[7] = {1, 1, 1, 1, 2, 1, 2};
    const int pa0[7] = {AH, AS, AS, AN, AH, AH, AN};
    const int pa1[7] = {0, 0, 0, 0, AS, 0, AX};
    const int fillf[7] = {1, 0, 1, 1, 1, 1, 1};
    const int epi[7] = {-1, 0, 1, 2, 2, 2, 2};  // -1 none, 0 add, 1 *invdeg, 2 relu

    for (int j = 0; j < nst; j++) {
        const float* h = (j == 0) ? h0p : (j == 1) ? h1p : (j == 2) ? h2p : (j == 3) ? h3p : h4p;
        int ldh = (j == 0) ? l0 : (j == 1) ? l1 : (j == 2) ? l2 : (j == 3) ? l3 : l4;
        const float* ssum = sums + (size_t)j * NSZ;
        const float* snrm = nrms + (size_t)j * NSZ;
        const __nv_bfloat16* wslot = wbase + (size_t)j * 7 * 8192;

        __syncthreads();  // prev slot's MMA done reading A
#pragma unroll
        for (int i = 0; i < 8; i++) {
            int idx = tid + i * 256;
            int row = idx >> 4, cg = (idx & 15) * 4;
            int gm = m0 + row;
            float4 z = make_float4(0.f, 0.f, 0.f, 0.f);
            float4 hv = z, sv = z, nv = z;
            if (gm < NN) {
                hv = *(const float4*)(h + (size_t)gm * ldh + cg);
                sv = *(const float4*)(ssum + (size_t)gm * 64 + cg);
                nv = *(const float4*)(snrm + (size_t)gm * 64 + cg);
            }
            int off = row * 144 + cg * 2;
            store_split4(smc + AH + off, smc + AH + ALO + off, hv);
            store_split4(smc + AS + off, smc + AS + ALO + off, sv);
            store_split4(smc + AN + off, smc + AN + ALO + off, nv);
        }

        for (int p = 0; p < 7; p++) {
            __syncthreads();  // B free + (p==0) A tiles ready
            {   // copy panel p: hi 64 rows + lo 64 rows, 8 uint4 per row
                const uint4* src = (const uint4*)(wslot + p * 8192);
#pragma unroll
                for (int i = 0; i < 4; i++) {
                    int u = tid + i * 256;
                    int r = u >> 3, c = u & 7;
                    int dst = (r < 64) ? (BHI + r * 144 + c * 16) : (BLO + (r - 64) * 144 + c * 16);
                    *(uint4*)(smc + dst) = src[u];
                }
            }
            __syncthreads();
            if (fillf[p]) {
#pragma unroll
                for (int nf = 0; nf < 4; nf++) wmma::fill_fragment(fc[nf], 0.f);
            }
            mma_pass(fc, smc, pa0[p], BHI, wrow);          // Ahi x Bhi
            mma_pass(fc, smc, pa0[p], BLO, wrow);          // Ahi x Blo
            mma_pass(fc, smc, pa0[p] + ALO, BHI, wrow);    // Alo x Bhi
            if (na[p] == 2) {
                mma_pass(fc, smc, pa1[p], BHI, wrow);
                mma_pass(fc, smc, pa1[p], BLO, wrow);
                mma_pass(fc, smc, pa1[p] + ALO, BHI, wrow);
            }
            int e = epi[p];
            if (e >= 0) {
#pragma unroll
                for (int nf = 0; nf < 4; nf++)
                    wmma::store_matrix_sync(cst + nf * 16, fc[nf], 68, wmma::mem_row_major);
                __syncwarp();
                const float4* rp = (const float4*)(cst + (lane >> 1) * 68 + (lane & 1) * 32);
#pragma unroll
                for (int i = 0; i < 8; i++) {
                    float4 v = rp[i];
                    if (e == 1) { v.x *= idg; v.y *= idg; v.z *= idg; v.w *= idg; }
                    else if (e == 2) {
                        v.x = fmaxf(v.x, 0.f); v.y = fmaxf(v.y, 0.f);
                        v.z = fmaxf(v.z, 0.f); v.w = fmaxf(v.w, 0.f);
                    }
                    outv[i * 4 + 0] += v.x; outv[i * 4 + 1] += v.y;
                    outv[i * 4 + 2] += v.z; outv[i * 4 + 3] += v.w;
                }
                __syncwarp();
            }
        }
    }
    if (mE < NN) {
        float* orow = outp + (size_t)mE * 256 + (lane & 1) * 32;
#pragma unroll
        for (int i = 0; i < 8; i++)
            *(float4*)(orow + i * 4) =
                make_float4(outv[i * 4], outv[i * 4 + 1], outv[i * 4 + 2], outv[i * 4 + 3]);
    }
}

__global__ void k_cls(const float* __restrict__ s1, const float* __restrict__ W,
                      const float* __restrict__ b, float* __restrict__ out) {
    int n = blockIdx.x;
    __shared__ float row[256];
    __shared__ float red[64];
    int tid = threadIdx.x;
    float ls = 0.f;
#pragma unroll
    for (int i = 0; i < 4; i++) {
        float v = s1[(size_t)n * 256 + tid + i * 64];
        row[tid + i * 64] = v;
        ls += v;
    }
    red[tid] = ls;
    __syncthreads();
    for (int off = 32; off > 0; off >>= 1) {
        if (tid < off) red[tid] += red[tid + off];
        __syncthreads();
    }
    float pooled = red[0] * (1.0f / 256.0f);
    if (tid < 40) {
        float acc = b[tid] + pooled * W[tid];
#pragma unroll 8
        for (int k = 0; k < 256; k++) acc += row[k] * W[(1 + k) * 40 + tid];
        out[(size_t)n * 40 + tid] = acc;
    }
}

static void bnrun(float* buf, int ncols, int dorelu, float* part, float* stats) {
    k_colstats<<<NBLK_STATS, 192>>>(buf, ncols, part);
    k_colfin<<<1, 192>>>(part, ncols, stats);
    size_t total = (size_t)NN * ncols;
    k_bnapply<<<(int)((total + 255) / 256), 256>>>(buf, ncols, stats, dorelu);
}

extern "C" void kernel_launch(void* const* d_in, const int* in_sizes, int n_in,
                              void* d_out, int out_size) {
    const float* x = (const float*)d_in[0];
    const int* ei = (const int*)d_in[1];
    const float* alphas = (const float*)d_in[2];
    const float* stemW = (const float*)d_in[3];
    const float* preW = (const float*)d_in[4];
    const float* p0W0 = (const float*)d_in[5];
    const float* p1W0 = (const float*)d_in[6];
    const float* p0W1 = (const float*)d_in[7];
    const float* p1W1 = (const float*)d_in[8];
    const float* Wgcn = (const float*)d_in[9];
    const float* Wss = (const float*)d_in[10];
    const float* Wsn = (const float*)d_in[11];
    const float* Wgin = (const float*)d_in[12];
    const float* Wgc1 = (const float*)d_in[13];
    const float* Wgc2 = (const float*)d_in[14];
    const float* Wmlp = (const float*)d_in[15];
    const float* Wgcnii = (const float*)d_in[16];
    const float* clsW = (const float*)d_in[17];
    const float* clsb = (const float*)d_in[18];
    float* out = (float*)d_out;
    const int* srcI = ei;
    const int* dstI = ei + EE;

    float *stem, *x0p, *ap, *bp, *c0, *c1, *sums, *nrms, *wmix, *stats, *part;
    float *invdeg, *invsqrt, *ew;
    __nv_bfloat16* wbk;
    int *deg, *cursor, *rowptr, *eid, *srcs, *bsum;
    cudaGetSymbolAddress((void**)&stem, g_stem);
    cudaGetSymbolAddress((void**)&x0p, g_x0);
    cudaGetSymbolAddress((void**)&ap, g_a);
    cudaGetSymbolAddress((void**)&bp, g_b);
    cudaGetSymbolAddress((void**)&c0, g_cell0);
    cudaGetSymbolAddress((void**)&c1, g_cell1);
    cudaGetSymbolAddress((void**)&sums, g_sum);
    cudaGetSymbolAddress((void**)&nrms, g_nrm);
    cudaGetSymbolAddress((void**)&wbk, g_wbk);
    cudaGetSymbolAddress((void**)&wmix, g_wmix);
    cudaGetSymbolAddress((void**)&stats, g_stats);
    cudaGetSymbolAddress((void**)&part, g_part);
    cudaGetSymbolAddress((void**)&invdeg, g_invdeg);
    cudaGetSymbolAddress((void**)&invsqrt, g_invsqrt);
    cudaGetSymbolAddress((void**)&ew, g_ew);
    cudaGetSymbolAddress((void**)&deg, g_deg);
    cudaGetSymbolAddress((void**)&cursor, g_cursor);
    cudaGetSymbolAddress((void**)&rowptr, g_rowptr);
    cudaGetSymbolAddress((void**)&eid, g_eid);
    cudaGetSymbolAddress((void**)&srcs, g_srcs);
    cudaGetSymbolAddress((void**)&bsum, g_bsum);

    cudaFuncSetAttribute(k_step, cudaFuncAttributeMaxDynamicSharedMemorySize, STEP_SMEM);

    k_zero2<<<(NN + 255) / 256, 256>>>(deg, cursor);
    k_deg<<<(EE + 255) / 256, 256>>>(dstI, deg);
    k_degfin<<<(NN + 255) / 256, 256>>>(deg, invdeg, invsqrt);
    k_scan1<<<SCAN_B, 128>>>(deg, rowptr, bsum);
    k_scan2<<<1, 512>>>(bsum);
    k_scan3<<<(NN + 255) / 256, 256>>>(rowptr, bsum);
    k_scatter<<<(EE + 255) / 256, 256>>>(dstI, rowptr, cursor, eid);
    k_sortfill<<<(NN + 127) / 128, 128>>>(rowptr, eid, srcI, invsqrt, srcs, ew);

    k_softmax<<<1, 16>>>(alphas, wmix);
    k_bake<<<28, 256>>>(wmix, Wgcn, Wss, Wsn, Wgin, Wgc1, Wgc2, Wmlp, Wgcnii, wbk);

    k_gemm<<<dim3(MT64, 3), 256>>>(x, 128, stemW, 192, stem, 128);
    bnrun(stem, 192, 0, part, stats);
    k_gemm<<<dim3(MT64, 1), 256>>>(x, 128, preW, 64, x0p, 128);
    bnrun(x0p, 64, 1, part, stats);

    const int aggBlocks = (NN * 32 + 255) / 256;
    for (int ci = 0; ci < 2; ci++) {
        const float* s0 = stem; int k0 = 192;
        const float* s1 = (ci == 0) ? stem : c0;
        int k1 = (ci == 0) ? 192 : 256;
        const float* pW0 = (ci == 0) ? p0W0 : p0W1;
        const float* pW1 = (ci == 0) ? p1W0 : p1W1;
        float* cell = (ci == 0) ? c0 : c1;

        k_gemm<<<dim3(MT64, 1), 256>>>(s0, k0, pW0, 64, ap, k0);
        bnrun(ap, 64, 1, part, stats);
        k_gemm<<<dim3(MT64, 1), 256>>>(s1, k1, pW1, 64, bp, k1);
        bnrun(bp, 64, 1, part, stats);

        const float* sp[5] = {ap, bp, cell, cell + 64, cell + 128};
        const int sl[5] = {64, 64, 256, 256, 256};
        k_agg<<<aggBlocks, 256>>>(sp[0], sl[0], rowptr, srcs, ew, sums, nrms);
        k_agg<<<aggBlocks, 256>>>(sp[1], sl[1], rowptr, srcs, ew, sums + (size_t)NSZ, nrms + (size_t)NSZ);

        int ej0 = 0;
        for (int t = 0; t < 4; t++) {
            const __nv_bfloat16* wb = wbk + (size_t)(ci * 14 + ej0) * 7 * 8192;
            k_step<<<MT128, 256, STEP_SMEM>>>(sp[0], sp[1], sp[2], sp[3], sp[4],
                                              sl[0], sl[1], sl[2], sl[3], sl[4],
                                              sums, nrms, x0p, invdeg, wb, t + 2, cell + t * 64);
            ej0 += t + 2;
            if (t < 3) {
                int ns = t + 2;
                k_agg<<<aggBlocks, 256>>>(sp[ns], sl[ns], rowptr, srcs, ew,
                                          sums + (size_t)ns * NSZ, nrms + (size_t)ns * NSZ);
            }
        }
    }
    k_cls<<<NN, 64>>>(c1, clsW, clsb, out);
}

// round 8
// speedup vs baseline: 1.5491x; 1.0291x over previous
#include <cuda_runtime.h>
#include <cuda_bf16.h>
#include <mma.h>
#include <math.h>
using namespace nvcuda;

#define NN 50000
#define EE 800000
#define MT64 ((NN + 63) / 64)
#define MT128 ((NN + 127) / 128)
#define NSZ (NN * 64)
#define NBLK_STATS 200
#define SCAN_B ((NN + 127) / 128)
#define TS 4352
typedef unsigned int u32;

// smem byte offsets for k_step (A stride 72 bf16 = 144B/row, 128 rows = 18432B/tile)
#define AH 0
#define AS 36864
#define AN 73728
#define AX 110592
#define ALO 18432          // lo tile offset relative to hi
#define B0OF 147456
#define B1OF 165888
#define CST 184320         // 8 warps x 4352B
#define STEP_SMEM 219136

__device__ __forceinline__ void bsplit(float x, unsigned short& hb, unsigned short& lb) {
    __nv_bfloat16 h = __float2bfloat16_rn(x);
    float r = x - __bfloat162float(h);
    __nv_bfloat16 l = __float2bfloat16_rn(r);
    hb = *(unsigned short*)&h;
    lb = *(unsigned short*)&l;
}
__device__ __forceinline__ void store_split4(char* hp, char* lp, float4 v) {
    unsigned short h0, l0, h1, l1, h2, l2, h3, l3;
    bsplit(v.x, h0, l0); bsplit(v.y, h1, l1); bsplit(v.z, h2, l2); bsplit(v.w, h3, l3);
    *(uint2*)hp = make_uint2(((u32)h1 << 16) | h0, ((u32)h3 << 16) | h2);
    *(uint2*)lp = make_uint2(((u32)l1 << 16) | l0, ((u32)l3 << 16) | l2);
}

__device__ float g_stem[(size_t)NN * 192];
__device__ float g_x0[(size_t)NN * 64];
__device__ float g_a[(size_t)NN * 64];
__device__ float g_b[(size_t)NN * 64];
__device__ float g_cell0[(size_t)NN * 256];
__device__ float g_cell1[(size_t)NN * 256];
__device__ float g_sum[(size_t)5 * NSZ];
__device__ float g_nrm[(size_t)5 * NSZ];
__device__ __nv_bfloat16 g_wbk[(size_t)28 * 7 * 8192];  // per panel: hi[64][64] then lo[64][64]
__device__ float g_wmix[14 * 8];
__device__ float g_stats[384];
__device__ float g_part[NBLK_STATS * 384];
__device__ float g_invdeg[NN];
__device__ float g_invsqrt[NN];
__device__ float g_ew[EE];
__device__ int g_deg[NN];
__device__ int g_cursor[NN];
__device__ int g_rowptr[NN + 1];
__device__ int g_eid[EE];
__device__ int g_srcs[EE];
__device__ int g_bsum[512];

// ---------------- CSR ----------------
__global__ void k_zero2(int* a, int* b) {
    int i = blockIdx.x * blockDim.x + threadIdx.x;
    if (i < NN) { a[i] = 0; b[i] = 0; }
}
__global__ void k_deg(const int* __restrict__ dst, int* __restrict__ deg) {
    int e = blockIdx.x * blockDim.x + threadIdx.x;
    if (e < EE) atomicAdd(&deg[dst[e]], 1);
}
__global__ void k_degfin(const int* __restrict__ deg, float* __restrict__ invdeg,
                         float* __restrict__ invsqrt) {
    int i = blockIdx.x * blockDim.x + threadIdx.x;
    if (i < NN) {
        float d = (float)max(deg[i], 1);
        invdeg[i] = 1.0f / d;
        invsqrt[i] = rsqrtf(d);
    }
}
__global__ void k_scan1(const int* __restrict__ deg, int* __restrict__ rowptr, int* __restrict__ bsum) {
    __shared__ int s[128];
    int b = blockIdx.x, t = threadIdx.x;
    int i = b * 128 + t;
    int v = (i < NN) ? deg[i] : 0;
    s[t] = v;
    __syncthreads();
    for (int off = 1; off < 128; off <<= 1) {
        int u = (t >= off) ? s[t - off] : 0;
        __syncthreads();
        s[t] += u;
        __syncthreads();
    }
    if (i < NN) rowptr[i] = s[t] - v;
    if (t == 127) bsum[b] = s[127];
}
__global__ void k_scan2(int* __restrict__ bsum) {
    __shared__ int s[512];
    int t = threadIdx.x;
    int v = (t < SCAN_B) ? bsum[t] : 0;
    s[t] = v;
    __syncthreads();
    for (int off = 1; off < 512; off <<= 1) {
        int u = (t >= off) ? s[t - off] : 0;
        __syncthreads();
        s[t] += u;
        __syncthreads();
    }
    if (t < SCAN_B) bsum[t] = s[t] - v;
}
__global__ void k_scan3(int* __restrict__ rowptr, const int* __restrict__ bsum) {
    int i = blockIdx.x * blockDim.x + threadIdx.x;
    if (i < NN) rowptr[i] += bsum[i >> 7];
    if (i == 0) rowptr[NN] = EE;
}
__global__ void k_scatter(const int* __restrict__ dst, const int* __restrict__ rowptr,
                          int* __restrict__ cursor, int* __restrict__ eid) {
    int e = blockIdx.x * blockDim.x + threadIdx.x;
    if (e < EE) {
        int d = dst[e];
        int pos = rowptr[d] + atomicAdd(&cursor[d], 1);
        eid[pos] = e;
    }
}
__global__ void k_sortfill(const int* __restrict__ rowptr, int* __restrict__ eid,
                           const int* __restrict__ src, const float* __restrict__ invsqrt,
                           int* __restrict__ srcs, float* __restrict__ ew) {
    int n = blockIdx.x * blockDim.x + threadIdx.x;
    if (n >= NN) return;
    int r0 = rowptr[n], r1 = rowptr[n + 1];
    for (int i = r0 + 1; i < r1; i++) {
        int key = eid[i];
        int j = i - 1;
        while (j >= r0 && eid[j] > key) { eid[j + 1] = eid[j]; j--; }
        eid[j + 1] = key;
    }
    float isd = invsqrt[n];
    for (int p = r0; p < r1; p++) {
        int e = eid[p];
        int s = src[e];
        srcs[p] = s;
        ew[p] = invsqrt[s] * isd;
    }
}
__global__ void k_softmax(const float* __restrict__ alphas, float* __restrict__ wmix) {
    int r = threadIdx.x;
    if (r >= 14) return;
    float m = -1e30f;
    for (int o = 0; o < 8; o++) m = fmaxf(m, alphas[r * 8 + o]);
    float e[8], s = 0.f;
    for (int o = 0; o < 8; o++) { e[o] = expf(alphas[r * 8 + o] - m); s += e[o]; }
    float inv = 1.0f / s;
    for (int o = 0; o < 8; o++) wmix[r * 8 + o] = e[o] * inv;
}

// bake 7 bf16-split B panels per slot. Panel p, [k][n] row-major, hi 4096 then lo 4096 bf16.
__global__ void k_bake(const float* __restrict__ wmix,
                       const float* __restrict__ Wgcn, const float* __restrict__ Wss,
                       const float* __restrict__ Wsn, const float* __restrict__ Wgin,
                       const float* __restrict__ Wgc1, const float* __restrict__ Wgc2,
                       const float* __restrict__ Wmlp, const float* __restrict__ Wgcnii,
                       __nv_bfloat16* __restrict__ wbk) {
    int s = blockIdx.x;
    int ej = s % 14;
    const float* wv = wmix + ej * 8;
    size_t o = (size_t)s * 4096;
    __nv_bfloat16* ob = wbk + (size_t)s * 7 * 8192;
    float w1 = wv[1], w2 = wv[2], w3 = wv[3], w4 = wv[4], w5 = wv[5], w6 = wv[6], w7 = wv[7];
    for (int idx = threadIdx.x; idx < 4096; idx += blockDim.x) {
        int k = idx >> 6, n = idx & 63;
        for (int p = 0; p < 7; p++) {
            float v;
            if (p == 0) v = w3 * Wss[o + idx] + w5 * Wgc1[o + idx] + ((k == n) ? w1 : 0.f);
            else if (p == 1) v = w5 * Wgc2[o + idx];
            else if (p == 2) v = w3 * Wsn[o + idx];
            else if (p == 3) v = w2 * Wgcn[o + idx];
            else if (p == 4) v = w4 * Wgin[o + idx];
            else if (p == 5) v = w6 * Wmlp[o + idx];
            else v = 0.9f * w7 * Wgcnii[o + idx];
            unsigned short hb, lb;
            bsplit(v, hb, lb);
            ob[p * 8192 + idx] = *(__nv_bfloat16*)&hb;
            ob[p * 8192 + 4096 + idx] = *(__nv_bfloat16*)&lb;
        }
    }
}

// ---------------- fp32 tiled GEMM (stem/pre) ----------------
__global__ __launch_bounds__(256) void k_gemm(const float* __restrict__ A, int lda,
                                              const float* __restrict__ B, int ldb,
                                              float* __restrict__ C, int K) {
    __shared__ float As[TS];
    __shared__ float Bs[TS];
    const int tid = threadIdx.x;
    const int m0 = blockIdx.x * 64;
    const int n0b = blockIdx.y * 64;
    const int n0 = (tid & 15) * 4, mm0 = (tid >> 4) * 4;
    float acc[16];
#pragma unroll
    for (int i = 0; i < 16; i++) acc[i] = 0.f;
    for (int kt = 0; kt < K; kt += 64) {
        __syncthreads();
#pragma unroll
        for (int i = 0; i < 16; i++) {
            int idx = tid + i * 256;
            int m = idx >> 6, k = idx & 63;
            int gm = m0 + m;
            As[k * 68 + m] = (gm < NN) ? A[(size_t)gm * lda + kt + k] : 0.f;
            Bs[(idx >> 6) * 68 + (idx & 63)] = B[(size_t)(kt + (idx >> 6)) * ldb + n0b + (idx & 63)];
        }
        __syncthreads();
#pragma unroll 16
        for (int k = 0; k < 64; k++) {
            float4 a4 = *(const float4*)&As[k * 68 + mm0];
            float4 b4 = *(const float4*)&Bs[k * 68 + n0];
            acc[0] += a4.x * b4.x; acc[1] += a4.x * b4.y; acc[2] += a4.x * b4.z; acc[3] += a4.x * b4.w;
            acc[4] += a4.y * b4.x; acc[5] += a4.y * b4.y; acc[6] += a4.y * b4.z; acc[7] += a4.y * b4.w;
            acc[8] += a4.z * b4.x; acc[9] += a4.z * b4.y; acc[10] += a4.z * b4.z; acc[11] += a4.z * b4.w;
            acc[12] += a4.w * b4.x; acc[13] += a4.w * b4.y; acc[14] += a4.w * b4.z; acc[15] += a4.w * b4.w;
        }
    }
#pragma unroll
    for (int r = 0; r < 4; r++) {
        int gm = m0 + mm0 + r;
        if (gm < NN)
            *(float4*)&C[(size_t)gm * ldb + n0b + n0] =
                make_float4(acc[r * 4], acc[r * 4 + 1], acc[r * 4 + 2], acc[r * 4 + 3]);
    }
}

// ---------------- batchnorm ----------------
__global__ void k_colstats(const float* __restrict__ A, int ncols, float* __restrict__ part) {
    int blk = blockIdx.x, c = threadIdx.x;
    int rows_per = (NN + NBLK_STATS - 1) / NBLK_STATS;
    int r0 = blk * rows_per, r1 = min(NN, r0 + rows_per);
    float s = 0.f, s2 = 0.f;
    if (c < ncols)
        for (int r = r0; r < r1; r++) {
            float v = A[(size_t)r * ncols + c];
            s += v; s2 += v * v;
        }
    part[blk * 384 + c] = s;
    part[blk * 384 + 192 + c] = s2;
}
__global__ void k_colfin(const float* __restrict__ part, int ncols, float* __restrict__ stats) {
    int c = threadIdx.x;
    if (c >= ncols) return;
    float s = 0.f, s2 = 0.f;
    for (int b = 0; b < NBLK_STATS; b++) { s += part[b * 384 + c]; s2 += part[b * 384 + 192 + c]; }
    float m = s / (float)NN;
    float v = s2 / (float)NN - m * m;
    stats[c] = m;
    stats[192 + c] = rsqrtf(v + 1e-5f);
}
__global__ void k_bnapply(float* __restrict__ A, int ncols, const float* __restrict__ stats, int dorelu) {
    size_t idx = (size_t)blockIdx.x * blockDim.x + threadIdx.x;
    if (idx >= (size_t)NN * ncols) return;
    int c = (int)(idx % ncols);
    float v = (A[idx] - stats[c]) * stats[192 + c];
    if (dorelu) v = fmaxf(v, 0.f);
    A[idx] = v;
}
__global__ void k_agg(const float* __restrict__ h, int ldh, const int* __restrict__ rowptr,
                      const int* __restrict__ srcs, const float* __restrict__ ew,
                      float* __restrict__ osum, float* __restrict__ onrm) {
    int warp = (blockIdx.x * blockDim.x + threadIdx.x) >> 5;
    if (warp >= NN) return;
    int lane = threadIdx.x & 31;
    int r0 = rowptr[warp], r1 = rowptr[warp + 1];
    float2 s = make_float2(0.f, 0.f), nrm = make_float2(0.f, 0.f);
    for (int p = r0; p < r1; p++) {
        int si = srcs[p];
        float w = ew[p];
        float2 v = *(const float2*)&h[(size_t)si * ldh + lane * 2];
        s.x += v.x; s.y += v.y;
        nrm.x += w * v.x; nrm.y += w * v.y;
    }
    *(float2*)&osum[(size_t)warp * 64 + lane * 2] = s;
    *(float2*)&onrm[(size_t)warp * 64 + lane * 2] = nrm;
}

// ---------------- wmma bf16-split step kernel (B-frag reuse + B prefetch) ----------------
typedef wmma::fragment<wmma::matrix_a, 16, 16, 16, __nv_bfloat16, wmma::row_major> FragA;
typedef wmma::fragment<wmma::matrix_b, 16, 16, 16, __nv_bfloat16, wmma::row_major> FragB;
typedef wmma::fragment<wmma::accumulator, 16, 16, 16, float> FragC;

__global__ __launch_bounds__(256, 1) void k_step(
    const float* __restrict__ h0p, const float* __restrict__ h1p, const float* __restrict__ h2p,
    const float* __restrict__ h3p, const float* __restrict__ h4p,
    int l0, int l1, int l2, int l3, int l4,
    const float* __restrict__ sums, const float* __restrict__ nrms,
    const float* __restrict__ x0, const float* __restrict__ invdeg,
    const __nv_bfloat16* __restrict__ wbase, int nst, float* __restrict__ outp) {
    extern __shared__ char smc[];
    const int tid = threadIdx.x, wid = tid >> 5, lane = tid & 31;
    const int m0 = blockIdx.x * 128;
    const int wrow = wid * 16;
    const int mE = m0 + wrow + (lane >> 1);
    const float idg = (mE < NN) ? invdeg[mE] : 0.f;
    float* cst = (float*)(smc + CST + wid * 4352);

    // x0/9 tile, built once
#pragma unroll
    for (int i = 0; i < 8; i++) {
        int idx = tid + i * 256;
        int row = idx >> 4, cg = (idx & 15) * 4;
        int gm = m0 + row;
        float4 xv = (gm < NN) ? *(const float4*)(x0 + (size_t)gm * 64 + cg)
                              : make_float4(0.f, 0.f, 0.f, 0.f);
        const float s9 = 1.0f / 9.0f;
        xv.x *= s9; xv.y *= s9; xv.z *= s9; xv.w *= s9;
        int off = row * 144 + cg * 2;
        store_split4(smc + AX + off, smc + AX + ALO + off, xv);
    }

    float outv[32];
#pragma unroll
    for (int i = 0; i < 32; i++) outv[i] = 0.f;
    FragC fc[4];
    uint4 pf[4];
    {   // initial prefetch: slot 0 panel 0
        const uint4* s = (const uint4*)wbase;
#pragma unroll
        for (int i = 0; i < 4; i++) pf[i] = s[tid + i * 256];
    }

    const int na[7] = {1, 1, 1, 1, 2, 1, 2};
    const int pa0[7] = {AH, AS, AS, AN, AH, AH, AN};
    const int pa1[7] = {0, 0, 0, 0, AS, 0, AX};
    const int fillf[7] = {1, 0, 1, 1, 1, 1, 1};
    const int epi[7] = {-1, 0, 1, 2, 2, 2, 2};  // -1 none, 0 add, 1 *invdeg, 2 relu

    for (int j = 0; j < nst; j++) {
        const float* h = (j == 0) ? h0p : (j == 1) ? h1p : (j == 2) ? h2p : (j == 3) ? h3p : h4p;
        int ldh = (j == 0) ? l0 : (j == 1) ? l1 : (j == 2) ? l2 : (j == 3) ? l3 : l4;
        const float* ssum = sums + (size_t)j * NSZ;
        const float* snrm = nrms + (size_t)j * NSZ;
        const __nv_bfloat16* wslot = wbase + (size_t)j * 7 * 8192;

        __syncthreads();  // all MMA of prev slot done (A tiles + buf0 free)
#pragma unroll
        for (int i = 0; i < 8; i++) {
            int idx = tid + i * 256;
            int row = idx >> 4, cg = (idx & 15) * 4;
            int gm = m0 + row;
            float4 z = make_float4(0.f, 0.f, 0.f, 0.f);
            float4 hv = z, sv = z, nv = z;
            if (gm < NN) {
                hv = *(const float4*)(h + (size_t)gm * ldh + cg);
                sv = *(const float4*)(ssum + (size_t)gm * 64 + cg);
                nv = *(const float4*)(snrm + (size_t)gm * 64 + cg);
            }
            int off = row * 144 + cg * 2;
            store_split4(smc + AH + off, smc + AH + ALO + off, hv);
            store_split4(smc + AS + off, smc + AS + ALO + off, sv);
            store_split4(smc + AN + off, smc + AN + ALO + off, nv);
        }

        for (int p = 0; p < 7; p++) {
            const int bofs = (p & 1) ? B1OF : B0OF;
            // publish prefetched panel into buffer (safe: MMA p-2 done per sync chain)
#pragma unroll
            for (int i = 0; i < 4; i++) {
                int u = tid + i * 256;
                int r = u >> 3, c = u & 7;
                int dst = bofs + ((r < 64) ? (r * 144 + c * 16) : (9216 + (r - 64) * 144 + c * 16));
                *(uint4*)(smc + dst) = pf[i];
            }
            __syncthreads();
            // prefetch next panel (wslot+7*8192 == next slot's panel 0)
            if (p < 6 || j + 1 < nst) {
                const uint4* s = (const uint4*)(wslot + (size_t)(p + 1) * 8192);
#pragma unroll
                for (int i = 0; i < 4; i++) pf[i] = s[tid + i * 256];
            }
            if (fillf[p]) {
#pragma unroll
                for (int nf = 0; nf < 4; nf++) wmma::fill_fragment(fc[nf], 0.f);
            }
            const __nv_bfloat16* BH = (const __nv_bfloat16*)(smc + bofs);
            const __nv_bfloat16* BL = BH + 4608;
            const __nv_bfloat16* A0 = (const __nv_bfloat16*)(smc + pa0[p]) + wrow * 72;
            const __nv_bfloat16* A1 = (const __nv_bfloat16*)(smc + pa1[p]) + wrow * 72;
            const bool two = (na[p] == 2);
#pragma unroll
            for (int kc = 0; kc < 4; kc++) {
                FragB bh[4], bl[4];
#pragma unroll
                for (int nf = 0; nf < 4; nf++) {
                    wmma::load_matrix_sync(bh[nf], BH + kc * 1152 + nf * 16, 72);
                    wmma::load_matrix_sync(bl[nf], BL + kc * 1152 + nf * 16, 72);
                }
                FragA fa;
                wmma::load_matrix_sync(fa, A0 + kc * 16, 72);  // A hi
#pragma unroll
                for (int nf = 0; nf < 4; nf++) wmma::mma_sync(fc[nf], fa, bh[nf], fc[nf]);
#pragma unroll
                for (int nf = 0; nf < 4; nf++) wmma::mma_sync(fc[nf], fa, bl[nf], fc[nf]);
                wmma::load_matrix_sync(fa, A0 + 9216 + kc * 16, 72);  // A lo
#pragma unroll
                for (int nf = 0; nf < 4; nf++) wmma::mma_sync(fc[nf], fa, bh[nf], fc[nf]);
                if (two) {
                    wmma::load_matrix_sync(fa, A1 + kc * 16, 72);
#pragma unroll
                    for (int nf = 0; nf < 4; nf++) wmma::mma_sync(fc[nf], fa, bh[nf], fc[nf]);
#pragma unroll
                    for (int nf = 0; nf < 4; nf++) wmma::mma_sync(fc[nf], fa, bl[nf], fc[nf]);
                    wmma::load_matrix_sync(fa, A1 + 9216 + kc * 16, 72);
#pragma unroll
                    for (int nf = 0; nf < 4; nf++) wmma::mma_sync(fc[nf], fa, bh[nf], fc[nf]);
                }
            }
            int e = epi[p];
            if (e >= 0) {
#pragma unroll
                for (int nf = 0; nf < 4; nf++)
                    wmma::store_matrix_sync(cst + nf * 16, fc[nf], 68, wmma::mem_row_major);
                __syncwarp();
                const float4* rp = (const float4*)(cst + (lane >> 1) * 68 + (lane & 1) * 32);
#pragma unroll
                for (int i = 0; i < 8; i++) {
                    float4 v = rp[i];
                    if (e == 1) { v.x *= idg; v.y *= idg; v.z *= idg; v.w *= idg; }
                    else if (e == 2) {
                        v.x = fmaxf(v.x, 0.f); v.y = fmaxf(v.y, 0.f);
                        v.z = fmaxf(v.z, 0.f); v.w = fmaxf(v.w, 0.f);
                    }
                    outv[i * 4 + 0] += v.x; outv[i * 4 + 1] += v.y;
                    outv[i * 4 + 2] += v.z; outv[i * 4 + 3] += v.w;
                }
                __syncwarp();
            }
        }
    }
    if (mE < NN) {
        float* orow = outp + (size_t)mE * 256 + (lane & 1) * 32;
#pragma unroll
        for (int i = 0; i < 8; i++)
            *(float4*)(orow + i * 4) =
                make_float4(outv[i * 4], outv[i * 4 + 1], outv[i * 4 + 2], outv[i * 4 + 3]);
    }
}

__global__ void k_cls(const float* __restrict__ s1, const float* __restrict__ W,
                      const float* __restrict__ b, float* __restrict__ out) {
    int n = blockIdx.x;
    __shared__ float row[256];
    __shared__ float red[64];
    int tid = threadIdx.x;
    float ls = 0.f;
#pragma unroll
    for (int i = 0; i < 4; i++) {
        float v = s1[(size_t)n * 256 + tid + i * 64];
        row[tid + i * 64] = v;
        ls += v;
    }
    red[tid] = ls;
    __syncthreads();
    for (int off = 32; off > 0; off >>= 1) {
        if (tid < off) red[tid] += red[tid + off];
        __syncthreads();
    }
    float pooled = red[0] * (1.0f / 256.0f);
    if (tid < 40) {
        float acc = b[tid] + pooled * W[tid];
#pragma unroll 8
        for (int k = 0; k < 256; k++) acc += row[k] * W[(1 + k) * 40 + tid];
        out[(size_t)n * 40 + tid] = acc;
    }
}

static void bnrun(float* buf, int ncols, int dorelu, float* part, float* stats) {
    k_colstats<<<NBLK_STATS, 192>>>(buf, ncols, part);
    k_colfin<<<1, 192>>>(part, ncols, stats);
    size_t total = (size_t)NN * ncols;
    k_bnapply<<<(int)((total + 255) / 256), 256>>>(buf, ncols, stats, dorelu);
}

extern "C" void kernel_launch(void* const* d_in, const int* in_sizes, int n_in,
                              void* d_out, int out_size) {
    const float* x = (const float*)d_in[0];
    const int* ei = (const int*)d_in[1];
    const float* alphas = (const float*)d_in[2];
    const float* stemW = (const float*)d_in[3];
    const float* preW = (const float*)d_in[4];
    const float* p0W0 = (const float*)d_in[5];
    const float* p1W0 = (const float*)d_in[6];
    const float* p0W1 = (const float*)d_in[7];
    const float* p1W1 = (const float*)d_in[8];
    const float* Wgcn = (const float*)d_in[9];
    const float* Wss = (const float*)d_in[10];
    const float* Wsn = (const float*)d_in[11];
    const float* Wgin = (const float*)d_in[12];
    const float* Wgc1 = (const float*)d_in[13];
    const float* Wgc2 = (const float*)d_in[14];
    const float* Wmlp = (const float*)d_in[15];
    const float* Wgcnii = (const float*)d_in[16];
    const float* clsW = (const float*)d_in[17];
    const float* clsb = (const float*)d_in[18];
    float* out = (float*)d_out;
    const int* srcI = ei;
    const int* dstI = ei + EE;

    float *stem, *x0p, *ap, *bp, *c0, *c1, *sums, *nrms, *wmix, *stats, *part;
    float *invdeg, *invsqrt, *ew;
    __nv_bfloat16* wbk;
    int *deg, *cursor, *rowptr, *eid, *srcs, *bsum;
    cudaGetSymbolAddress((void**)&stem, g_stem);
    cudaGetSymbolAddress((void**)&x0p, g_x0);
    cudaGetSymbolAddress((void**)&ap, g_a);
    cudaGetSymbolAddress((void**)&bp, g_b);
    cudaGetSymbolAddress((void**)&c0, g_cell0);
    cudaGetSymbolAddress((void**)&c1, g_cell1);
    cudaGetSymbolAddress((void**)&sums, g_sum);
    cudaGetSymbolAddress((void**)&nrms, g_nrm);
    cudaGetSymbolAddress((void**)&wbk, g_wbk);
    cudaGetSymbolAddress((void**)&wmix, g_wmix);
    cudaGetSymbolAddress((void**)&stats, g_stats);
    cudaGetSymbolAddress((void**)&part, g_part);
    cudaGetSymbolAddress((void**)&invdeg, g_invdeg);
    cudaGetSymbolAddress((void**)&invsqrt, g_invsqrt);
    cudaGetSymbolAddress((void**)&ew, g_ew);
    cudaGetSymbolAddress((void**)&deg, g_deg);
    cudaGetSymbolAddress((void**)&cursor, g_cursor);
    cudaGetSymbolAddress((void**)&rowptr, g_rowptr);
    cudaGetSymbolAddress((void**)&eid, g_eid);
    cudaGetSymbolAddress((void**)&srcs, g_srcs);
    cudaGetSymbolAddress((void**)&bsum, g_bsum);

    cudaFuncSetAttribute(k_step, cudaFuncAttributeMaxDynamicSharedMemorySize, STEP_SMEM);

    k_zero2<<<(NN + 255) / 256, 256>>>(deg, cursor);
    k_deg<<<(EE + 255) / 256, 256>>>(dstI, deg);
    k_degfin<<<(NN + 255) / 256, 256>>>(deg, invdeg, invsqrt);
    k_scan1<<<SCAN_B, 128>>>(deg, rowptr, bsum);
    k_scan2<<<1, 512>>>(bsum);
    k_scan3<<<(NN + 255) / 256, 256>>>(rowptr, bsum);
    k_scatter<<<(EE + 255) / 256, 256>>>(dstI, rowptr, cursor, eid);
    k_sortfill<<<(NN + 127) / 128, 128>>>(rowptr, eid, srcI, invsqrt, srcs, ew);

    k_softmax<<<1, 16>>>(alphas, wmix);
    k_bake<<<28, 256>>>(wmix, Wgcn, Wss, Wsn, Wgin, Wgc1, Wgc2, Wmlp, Wgcnii, wbk);

    k_gemm<<<dim3(MT64, 3), 256>>>(x, 128, stemW, 192, stem, 128);
    bnrun(stem, 192, 0, part, stats);
    k_gemm<<<dim3(MT64, 1), 256>>>(x, 128, preW, 64, x0p, 128);
    bnrun(x0p, 64, 1, part, stats);

    const int aggBlocks = (NN * 32 + 255) / 256;
    for (int ci = 0; ci < 2; ci++) {
        const float* s0 = stem; int k0 = 192;
        const float* s1 = (ci == 0) ? stem : c0;
        int k1 = (ci == 0) ? 192 : 256;
        const float* pW0 = (ci == 0) ? p0W0 : p0W1;
        const float* pW1 = (ci == 0) ? p1W0 : p1W1;
        float* cell = (ci == 0) ? c0 : c1;

        k_gemm<<<dim3(MT64, 1), 256>>>(s0, k0, pW0, 64, ap, k0);
        bnrun(ap, 64, 1, part, stats);
        k_gemm<<<dim3(MT64, 1), 256>>>(s1, k1, pW1, 64, bp, k1);
        bnrun(bp, 64, 1, part, stats);

        const float* sp[5] = {ap, bp, cell, cell + 64, cell + 128};
        const int sl[5] = {64, 64, 256, 256, 256};
        k_agg<<<aggBlocks, 256>>>(sp[0], sl[0], rowptr, srcs, ew, sums, nrms);
        k_agg<<<aggBlocks, 256>>>(sp[1], sl[1], rowptr, srcs, ew, sums + (size_t)NSZ, nrms + (size_t)NSZ);

        int ej0 = 0;
        for (int t = 0; t < 4; t++) {
            const __nv_bfloat16* wb = wbk + (size_t)(ci * 14 + ej0) * 7 * 8192;
            k_step<<<MT128, 256, STEP_SMEM>>>(sp[0], sp[1], sp[2], sp[3], sp[4],
                                              sl[0], sl[1], sl[2], sl[3], sl[4],
                                              sums, nrms, x0p, invdeg, wb, t + 2, cell + t * 64);
            ej0 += t + 2;
            if (t < 3) {
                int ns = t + 2;
                k_agg<<<aggBlocks, 256>>>(sp[ns], sl[ns], rowptr, srcs, ew,
                                          sums + (size_t)ns * NSZ, nrms + (size_t)ns * NSZ);
            }
        }
    }
    k_cls<<<NN, 64>>>(c1, clsW, clsb, out);
}

// round 9
// speedup vs baseline: 1.5822x; 1.0214x over previous
#include <cuda_runtime.h>
#include <cuda_bf16.h>
#include <mma.h>
#include <math.h>
using namespace nvcuda;

#define NN 50000
#define EE 800000
#define MT64 ((NN + 63) / 64)
#define NSZ (NN * 64)
#define NBLK_STATS 200
#define SCAN_B ((NN + 127) / 128)
#define TS 4352
typedef unsigned int u32;

// k_step smem (bytes): 4 logical A tiles (64 rows x 72 bf16 stride; hi 9216 + lo 9216)
#define AH 0
#define AHS 18432
#define AN 36864
#define AG 55296
#define BOF 73728          // B hi 9216 + lo 9216
#define CST 92160          // 4 warps x 4352
#define STEP_SMEM 109568

__device__ __forceinline__ void bsplit(float x, unsigned short& hb, unsigned short& lb) {
    __nv_bfloat16 h = __float2bfloat16_rn(x);
    float r = x - __bfloat162float(h);
    __nv_bfloat16 l = __float2bfloat16_rn(r);
    hb = *(unsigned short*)&h;
    lb = *(unsigned short*)&l;
}
__device__ __forceinline__ void store_split4(char* hp, char* lp, float4 v) {
    unsigned short h0, l0, h1, l1, h2, l2, h3, l3;
    bsplit(v.x, h0, l0); bsplit(v.y, h1, l1); bsplit(v.z, h2, l2); bsplit(v.w, h3, l3);
    *(uint2*)hp = make_uint2(((u32)h1 << 16) | h0, ((u32)h3 << 16) | h2);
    *(uint2*)lp = make_uint2(((u32)l1 << 16) | l0, ((u32)l3 << 16) | l2);
}

__device__ float g_stem[(size_t)NN * 192];
__device__ float g_x0[(size_t)NN * 64];
__device__ float g_a[(size_t)NN * 64];
__device__ float g_b[(size_t)NN * 64];
__device__ float g_cell0[(size_t)NN * 256];
__device__ float g_cell1[(size_t)NN * 256];
__device__ float g_sum[(size_t)5 * NSZ];
__device__ float g_nrm[(size_t)5 * NSZ];
__device__ __nv_bfloat16 g_wbk[(size_t)28 * 8 * 8192];  // 8 panels: hi[64][64] then lo[64][64]
__device__ float g_wmix[14 * 8];
__device__ float g_stats[384];
__device__ float g_part[NBLK_STATS * 384];
__device__ float g_invdeg[NN];
__device__ float g_invsqrt[NN];
__device__ float g_ew[EE];
__device__ int g_deg[NN];
__device__ int g_cursor[NN];
__device__ int g_rowptr[NN + 1];
__device__ int g_eid[EE];
__device__ int g_srcs[EE];
__device__ int g_bsum[512];

// ---------------- CSR ----------------
__global__ void k_zero2(int* a, int* b) {
    int i = blockIdx.x * blockDim.x + threadIdx.x;
    if (i < NN) { a[i] = 0; b[i] = 0; }
}
__global__ void k_deg(const int* __restrict__ dst, int* __restrict__ deg) {
    int e = blockIdx.x * blockDim.x + threadIdx.x;
    if (e < EE) atomicAdd(&deg[dst[e]], 1);
}
__global__ void k_degfin(const int* __restrict__ deg, float* __restrict__ invdeg,
                         float* __restrict__ invsqrt) {
    int i = blockIdx.x * blockDim.x + threadIdx.x;
    if (i < NN) {
        float d = (float)max(deg[i], 1);
        invdeg[i] = 1.0f / d;
        invsqrt[i] = rsqrtf(d);
    }
}
__global__ void k_scan1(const int* __restrict__ deg, int* __restrict__ rowptr, int* __restrict__ bsum) {
    __shared__ int s[128];
    int b = blockIdx.x, t = threadIdx.x;
    int i = b * 128 + t;
    int v = (i < NN) ? deg[i] : 0;
    s[t] = v;
    __syncthreads();
    for (int off = 1; off < 128; off <<= 1) {
        int u = (t >= off) ? s[t - off] : 0;
        __syncthreads();
        s[t] += u;
        __syncthreads();
    }
    if (i < NN) rowptr[i] = s[t] - v;
    if (t == 127) bsum[b] = s[127];
}
__global__ void k_scan2(int* __restrict__ bsum) {
    __shared__ int s[512];
    int t = threadIdx.x;
    int v = (t < SCAN_B) ? bsum[t] : 0;
    s[t] = v;
    __syncthreads();
    for (int off = 1; off < 512; off <<= 1) {
        int u = (t >= off) ? s[t - off] : 0;
        __syncthreads();
        s[t] += u;
        __syncthreads();
    }
    if (t < SCAN_B) bsum[t] = s[t] - v;
}
__global__ void k_scan3(int* __restrict__ rowptr, const int* __restrict__ bsum) {
    int i = blockIdx.x * blockDim.x + threadIdx.x;
    if (i < NN) rowptr[i] += bsum[i >> 7];
    if (i == 0) rowptr[NN] = EE;
}
__global__ void k_scatter(const int* __restrict__ dst, const int* __restrict__ rowptr,
                          int* __restrict__ cursor, int* __restrict__ eid) {
    int e = blockIdx.x * blockDim.x + threadIdx.x;
    if (e < EE) {
        int d = dst[e];
        int pos = rowptr[d] + atomicAdd(&cursor[d], 1);
        eid[pos] = e;
    }
}
__global__ void k_sortfill(const int* __restrict__ rowptr, int* __restrict__ eid,
                           const int* __restrict__ src, const float* __restrict__ invsqrt,
                           int* __restrict__ srcs, float* __restrict__ ew) {
    int n = blockIdx.x * blockDim.x + threadIdx.x;
    if (n >= NN) return;
    int r0 = rowptr[n], r1 = rowptr[n + 1];
    for (int i = r0 + 1; i < r1; i++) {
        int key = eid[i];
        int j = i - 1;
        while (j >= r0 && eid[j] > key) { eid[j + 1] = eid[j]; j--; }
        eid[j + 1] = key;
    }
    float isd = invsqrt[n];
    for (int p = r0; p < r1; p++) {
        int e = eid[p];
        int s = src[e];
        srcs[p] = s;
        ew[p] = invsqrt[s] * isd;
    }
}
__global__ void k_softmax(const float* __restrict__ alphas, float* __restrict__ wmix) {
    int r = threadIdx.x;
    if (r >= 14) return;
    float m = -1e30f;
    for (int o = 0; o < 8; o++) m = fmaxf(m, alphas[r * 8 + o]);
    float e[8], s = 0.f;
    for (int o = 0; o < 8; o++) { e[o] = expf(alphas[r * 8 + o] - m); s += e[o]; }
    float inv = 1.0f / s;
    for (int o = 0; o < 8; o++) wmix[r * 8 + o] = e[o] * inv;
}

// bake 8 bf16-split B panels/slot, [k][n] row-major, hi 4096 then lo 4096 bf16.
// A sources: p0:h p1:hs p2:hs p3:h p4:norm p5:hs p6:h p7:gmix
__global__ void k_bake(const float* __restrict__ wmix,
                       const float* __restrict__ Wgcn, const float* __restrict__ Wss,
                       const float* __restrict__ Wsn, const float* __restrict__ Wgin,
                       const float* __restrict__ Wgc1, const float* __restrict__ Wgc2,
                       const float* __restrict__ Wmlp, const float* __restrict__ Wgcnii,
                       __nv_bfloat16* __restrict__ wbk) {
    int s = blockIdx.x;
    int ej = s % 14;
    const float* wv = wmix + ej * 8;
    size_t o = (size_t)s * 4096;
    __nv_bfloat16* ob = wbk + (size_t)s * 8 * 8192;
    float w1 = wv[1], w2 = wv[2], w3 = wv[3], w4 = wv[4], w5 = wv[5], w6 = wv[6], w7 = wv[7];
    for (int idx = threadIdx.x; idx < 4096; idx += blockDim.x) {
        int k = idx >> 6, n = idx & 63;
        for (int p = 0; p < 8; p++) {
            float v;
            if (p == 0) v = w3 * Wss[o + idx] + w5 * (Wgc1[o + idx] - Wgc2[o + idx]) + ((k == n) ? w1 : 0.f);
            else if (p == 1) v = w5 * Wgc2[o + idx];
            else if (p == 2) v = w3 * Wsn[o + idx];
            else if (p == 3) v = -w3 * Wsn[o + idx];
            else if (p == 4) v = w2 * Wgcn[o + idx];
            else if (p == 5) v = w4 * Wgin[o + idx];
            else if (p == 6) v = w6 * Wmlp[o + idx];
            else v = w7 * Wgcnii[o + idx];
            unsigned short hb, lb;
            bsplit(v, hb, lb);
            ob[p * 8192 + idx] = *(__nv_bfloat16*)&hb;
            ob[p * 8192 + 4096 + idx] = *(__nv_bfloat16*)&lb;
        }
    }
}

// ---------------- fp32 tiled GEMM (stem/pre) ----------------
__global__ __launch_bounds__(256) void k_gemm(const float* __restrict__ A, int lda,
                                              const float* __restrict__ B, int ldb,
                                              float* __restrict__ C, int K) {
    __shared__ float As[TS];
    __shared__ float Bs[TS];
    const int tid = threadIdx.x;
    const int m0 = blockIdx.x * 64;
    const int n0b = blockIdx.y * 64;
    const int n0 = (tid & 15) * 4, mm0 = (tid >> 4) * 4;
    float acc[16];
#pragma unroll
    for (int i = 0; i < 16; i++) acc[i] = 0.f;
    for (int kt = 0; kt < K; kt += 64) {
        __syncthreads();
#pragma unroll
        for (int i = 0; i < 16; i++) {
            int idx = tid + i * 256;
            int m = idx >> 6, k = idx & 63;
            int gm = m0 + m;
            As[k * 68 + m] = (gm < NN) ? A[(size_t)gm * lda + kt + k] : 0.f;
            Bs[(idx >> 6) * 68 + (idx & 63)] = B[(size_t)(kt + (idx >> 6)) * ldb + n0b + (idx & 63)];
        }
        __syncthreads();
#pragma unroll 16
        for (int k = 0; k < 64; k++) {
            float4 a4 = *(const float4*)&As[k * 68 + mm0];
            float4 b4 = *(const float4*)&Bs[k * 68 + n0];
            acc[0] += a4.x * b4.x; acc[1] += a4.x * b4.y; acc[2] += a4.x * b4.z; acc[3] += a4.x * b4.w;
            acc[4] += a4.y * b4.x; acc[5] += a4.y * b4.y; acc[6] += a4.y * b4.z; acc[7] += a4.y * b4.w;
            acc[8] += a4.z * b4.x; acc[9] += a4.z * b4.y; acc[10] += a4.z * b4.z; acc[11] += a4.z * b4.w;
            acc[12] += a4.w * b4.x; acc[13] += a4.w * b4.y; acc[14] += a4.w * b4.z; acc[15] += a4.w * b4.w;
        }
    }
#pragma unroll
    for (int r = 0; r < 4; r++) {
        int gm = m0 + mm0 + r;
        if (gm < NN)
            *(float4*)&C[(size_t)gm * ldb + n0b + n0] =
                make_float4(acc[r * 4], acc[r * 4 + 1], acc[r * 4 + 2], acc[r * 4 + 3]);
    }
}

// ---------------- batchnorm ----------------
__global__ void k_colstats(const float* __restrict__ A, int ncols, float* __restrict__ part) {
    int blk = blockIdx.x, c = threadIdx.x;
    int rows_per = (NN + NBLK_STATS - 1) / NBLK_STATS;
    int r0 = blk * rows_per, r1 = min(NN, r0 + rows_per);
    float s = 0.f, s2 = 0.f;
    if (c < ncols)
        for (int r = r0; r < r1; r++) {
            float v = A[(size_t)r * ncols + c];
            s += v; s2 += v * v;
        }
    part[blk * 384 + c] = s;
    part[blk * 384 + 192 + c] = s2;
}
__global__ void k_colfin(const float* __restrict__ part, int ncols, float* __restrict__ stats) {
    int c = threadIdx.x;
    if (c >= ncols) return;
    float s = 0.f, s2 = 0.f;
    for (int b = 0; b < NBLK_STATS; b++) { s += part[b * 384 + c]; s2 += part[b * 384 + 192 + c]; }
    float m = s / (float)NN;
    float v = s2 / (float)NN - m * m;
    stats[c] = m;
    stats[192 + c] = rsqrtf(v + 1e-5f);
}
__global__ void k_bnapply(float* __restrict__ A, int ncols, const float* __restrict__ stats, int dorelu) {
    size_t idx = (size_t)blockIdx.x * blockDim.x + threadIdx.x;
    if (idx >= (size_t)NN * ncols) return;
    int c = (int)(idx % ncols);
    float v = (A[idx] - stats[c]) * stats[192 + c];
    if (dorelu) v = fmaxf(v, 0.f);
    A[idx] = v;
}
__global__ void k_agg(const float* __restrict__ h, int ldh, const int* __restrict__ rowptr,
                      const int* __restrict__ srcs, const float* __restrict__ ew,
                      float* __restrict__ osum, float* __restrict__ onrm) {
    int warp = (blockIdx.x * blockDim.x + threadIdx.x) >> 5;
    if (warp >= NN) return;
    int lane = threadIdx.x & 31;
    int r0 = rowptr[warp], r1 = rowptr[warp + 1];
    float2 s = make_float2(0.f, 0.f), nrm = make_float2(0.f, 0.f);
    for (int p = r0; p < r1; p++) {
        int si = srcs[p];
        float w = ew[p];
        float2 v = *(const float2*)&h[(size_t)si * ldh + lane * 2];
        s.x += v.x; s.y += v.y;
        nrm.x += w * v.x; nrm.y += w * v.y;
    }
    *(float2*)&osum[(size_t)warp * 64 + lane * 2] = s;
    *(float2*)&onrm[(size_t)warp * 64 + lane * 2] = nrm;
}

// ---------------- wmma bf16-split step kernel: 64-row CTA, 8 single-A panels ----------------
typedef wmma::fragment<wmma::matrix_a, 16, 16, 16, __nv_bfloat16, wmma::row_major> FragA;
typedef wmma::fragment<wmma::matrix_b, 16, 16, 16, __nv_bfloat16, wmma::row_major> FragB;
typedef wmma::fragment<wmma::accumulator, 16, 16, 16, float> FragC;

__global__ __launch_bounds__(128, 2) void k_step(
    const float* __restrict__ h0p, const float* __restrict__ h1p, const float* __restrict__ h2p,
    const float* __restrict__ h3p, const float* __restrict__ h4p,
    int l0, int l1, int l2, int l3, int l4,
    const float* __restrict__ sums, const float* __restrict__ nrms,
    const float* __restrict__ x0, const float* __restrict__ invdeg,
    const __nv_bfloat16* __restrict__ wbase, int nst, float* __restrict__ outp) {
    extern __shared__ char smc[];
    const int tid = threadIdx.x, wid = tid >> 5, lane = tid & 31;
    const int m0 = blockIdx.x * 64;
    const int wrow = wid * 16;
    const int mE = m0 + wrow + (lane >> 1);
    const float idg = (mE < NN) ? invdeg[mE] : 0.f;
    float* cst = (float*)(smc + CST + wid * 4352);

    float outv[32];
#pragma unroll
    for (int i = 0; i < 32; i++) outv[i] = 0.f;
    FragC fc[4];
    uint4 pf[8];
    {   // initial prefetch: slot 0 panel 0 (16KB -> 8 uint4/thread)
        const uint4* s = (const uint4*)wbase;
#pragma unroll
        for (int i = 0; i < 8; i++) pf[i] = s[tid + i * 128];
    }

    const int pa[8] = {AH, AHS, AHS, AH, AN, AHS, AH, AG};
    const int fillf[8] = {1, 0, 1, 0, 1, 1, 1, 1};
    const int epi[8] = {-1, 0, -1, 1, 2, 2, 2, 2};  // -1 none, 0 add, 1 *invdeg, 2 relu

    for (int j = 0; j < nst; j++) {
        const float* h = (j == 0) ? h0p : (j == 1) ? h1p : (j == 2) ? h2p : (j == 3) ? h3p : h4p;
        int ldh = (j == 0) ? l0 : (j == 1) ? l1 : (j == 2) ? l2 : (j == 3) ? l3 : l4;
        const float* ssum = sums + (size_t)j * NSZ;
        const float* snrm = nrms + (size_t)j * NSZ;
        const __nv_bfloat16* wslot = wbase + (size_t)j * 8 * 8192;

        __syncthreads();  // all MMA of prev slot done (A tiles free)
#pragma unroll
        for (int i = 0; i < 8; i++) {
            int idx = tid + i * 128;
            int row = idx >> 4, cg = (idx & 15) * 4;
            int gm = m0 + row;
            float4 z = make_float4(0.f, 0.f, 0.f, 0.f);
            float4 hv = z, sv = z, nv = z, xv = z;
            if (gm < NN) {
                hv = *(const float4*)(h + (size_t)gm * ldh + cg);
                sv = *(const float4*)(ssum + (size_t)gm * 64 + cg);
                nv = *(const float4*)(snrm + (size_t)gm * 64 + cg);
                xv = *(const float4*)(x0 + (size_t)gm * 64 + cg);
            }
            float4 hs = make_float4(hv.x + sv.x, hv.y + sv.y, hv.z + sv.z, hv.w + sv.w);
            float4 gv = make_float4(0.9f * nv.x + 0.1f * xv.x, 0.9f * nv.y + 0.1f * xv.y,
                                    0.9f * nv.z + 0.1f * xv.z, 0.9f * nv.w + 0.1f * xv.w);
            int off = row * 144 + cg * 2;
            store_split4(smc + AH + off, smc + AH + 9216 + off, hv);
            store_split4(smc + AHS + off, smc + AHS + 9216 + off, hs);
            store_split4(smc + AN + off, smc + AN + 9216 + off, nv);
            store_split4(smc + AG + off, smc + AG + 9216 + off, gv);
        }

        for (int p = 0; p < 8; p++) {
            __syncthreads();  // B free (prev panel MMA done); also separates A-build at p==0
            // publish prefetched panel: 1024 uint4; rows 0-63 hi, 64-127 lo
#pragma unroll
            for (int i = 0; i < 8; i++) {
                int u = tid + i * 128;
                int r = u >> 3, c = u & 7;
                int dst = BOF + ((r < 64) ? (r * 144 + c * 16) : (9216 + (r - 64) * 144 + c * 16));
                *(uint4*)(smc + dst) = pf[i];
            }
            __syncthreads();
            if (p < 7 || j + 1 < nst) {  // prefetch next panel (or next slot's panel 0)
                const uint4* s = (const uint4*)(wslot + (size_t)(p + 1) * 8192);
#pragma unroll
                for (int i = 0; i < 8; i++) pf[i] = s[tid + i * 128];
            }
            if (fillf[p]) {
#pragma unroll
                for (int nf = 0; nf < 4; nf++) wmma::fill_fragment(fc[nf], 0.f);
            }
            const __nv_bfloat16* BH = (const __nv_bfloat16*)(smc + BOF);
            const __nv_bfloat16* BL = BH + 4608;
            const __nv_bfloat16* A0 = (const __nv_bfloat16*)(smc + pa[p]) + wrow * 72;
#pragma unroll
            for (int kc = 0; kc < 4; kc++) {
                FragB bh[4], bl[4];
#pragma unroll
                for (int nf = 0; nf < 4; nf++) {
                    wmma::load_matrix_sync(bh[nf], BH + kc * 1152 + nf * 16, 72);
                    wmma::load_matrix_sync(bl[nf], BL + kc * 1152 + nf * 16, 72);
                }
                FragA fa;
                wmma::load_matrix_sync(fa, A0 + kc * 16, 72);  // A hi
#pragma unroll
                for (int nf = 0; nf < 4; nf++) wmma::mma_sync(fc[nf], fa, bh[nf], fc[nf]);
#pragma unroll
                for (int nf = 0; nf < 4; nf++) wmma::mma_sync(fc[nf], fa, bl[nf], fc[nf]);
                wmma::load_matrix_sync(fa, A0 + 4608 + kc * 16, 72);  // A lo
#pragma unroll
                for (int nf = 0; nf < 4; nf++) wmma::mma_sync(fc[nf], fa, bh[nf], fc[nf]);
            }
            int e = epi[p];
            if (e >= 0) {
#pragma unroll
                for (int nf = 0; nf < 4; nf++)
                    wmma::store_matrix_sync(cst + nf * 16, fc[nf], 68, wmma::mem_row_major);
                __syncwarp();
                const float4* rp = (const float4*)(cst + (lane >> 1) * 68 + (lane & 1) * 32);
#pragma unroll
                for (int i = 0; i < 8; i++) {
                    float4 v = rp[i];
                    if (e == 1) { v.x *= idg; v.y *= idg; v.z *= idg; v.w *= idg; }
                    else if (e == 2) {
                        v.x = fmaxf(v.x, 0.f); v.y = fmaxf(v.y, 0.f);
                        v.z = fmaxf(v.z, 0.f); v.w = fmaxf(v.w, 0.f);
                    }
                    outv[i * 4 + 0] += v.x; outv[i * 4 + 1] += v.y;
                    outv[i * 4 + 2] += v.z; outv[i * 4 + 3] += v.w;
                }
                __syncwarp();
            }
        }
    }
    if (mE < NN) {
        float* orow = outp + (size_t)mE * 256 + (lane & 1) * 32;
#pragma unroll
        for (int i = 0; i < 8; i++)
            *(float4*)(orow + i * 4) =
                make_float4(outv[i * 4], outv[i * 4 + 1], outv[i * 4 + 2], outv[i * 4 + 3]);
    }
}

__global__ void k_cls(const float* __restrict__ s1, const float* __restrict__ W,
                      const float* __restrict__ b, float* __restrict__ out) {
    int n = blockIdx.x;
    __shared__ float row[256];
    __shared__ float red[64];
    int tid = threadIdx.x;
    float ls = 0.f;
#pragma unroll
    for (int i = 0; i < 4; i++) {
        float v = s1[(size_t)n * 256 + tid + i * 64];
        row[tid + i * 64] = v;
        ls += v;
    }
    red[tid] = ls;
    __syncthreads();
    for (int off = 32; off > 0; off >>= 1) {
        if (tid < off) red[tid] += red[tid + off];
        __syncthreads();
    }
    float pooled = red[0] * (1.0f / 256.0f);
    if (tid < 40) {
        float acc = b[tid] + pooled * W[tid];
#pragma unroll 8
        for (int k = 0; k < 256; k++) acc += row[k] * W[(1 + k) * 40 + tid];
        out[(size_t)n * 40 + tid] = acc;
    }
}

static void bnrun(float* buf, int ncols, int dorelu, float* part, float* stats) {
    k_colstats<<<NBLK_STATS, 192>>>(buf, ncols, part);
    k_colfin<<<1, 192>>>(part, ncols, stats);
    size_t total = (size_t)NN * ncols;
    k_bnapply<<<(int)((total + 255) / 256), 256>>>(buf, ncols, stats, dorelu);
}

extern "C" void kernel_launch(void* const* d_in, const int* in_sizes, int n_in,
                              void* d_out, int out_size) {
    const float* x = (const float*)d_in[0];
    const int* ei = (const int*)d_in[1];
    const float* alphas = (const float*)d_in[2];
    const float* stemW = (const float*)d_in[3];
    const float* preW = (const float*)d_in[4];
    const float* p0W0 = (const float*)d_in[5];
    const float* p1W0 = (const float*)d_in[6];
    const float* p0W1 = (const float*)d_in[7];
    const float* p1W1 = (const float*)d_in[8];
    const float* Wgcn = (const float*)d_in[9];
    const float* Wss = (const float*)d_in[10];
    const float* Wsn = (const float*)d_in[11];
    const float* Wgin = (const float*)d_in[12];
    const float* Wgc1 = (const float*)d_in[13];
    const float* Wgc2 = (const float*)d_in[14];
    const float* Wmlp = (const float*)d_in[15];
    const float* Wgcnii = (const float*)d_in[16];
    const float* clsW = (const float*)d_in[17];
    const float* clsb = (const float*)d_in[18];
    float* out = (float*)d_out;
    const int* srcI = ei;
    const int* dstI = ei + EE;

    float *stem, *x0p, *ap, *bp, *c0, *c1, *sums, *nrms, *wmix, *stats, *part;
    float *invdeg, *invsqrt, *ew;
    __nv_bfloat16* wbk;
    int *deg, *cursor, *rowptr, *eid, *srcs, *bsum;
    cudaGetSymbolAddress((void**)&stem, g_stem);
    cudaGetSymbolAddress((void**)&x0p, g_x0);
    cudaGetSymbolAddress((void**)&ap, g_a);
    cudaGetSymbolAddress((void**)&bp, g_b);
    cudaGetSymbolAddress((void**)&c0, g_cell0);
    cudaGetSymbolAddress((void**)&c1, g_cell1);
    cudaGetSymbolAddress((void**)&sums, g_sum);
    cudaGetSymbolAddress((void**)&nrms, g_nrm);
    cudaGetSymbolAddress((void**)&wbk, g_wbk);
    cudaGetSymbolAddress((void**)&wmix, g_wmix);
    cudaGetSymbolAddress((void**)&stats, g_stats);
    cudaGetSymbolAddress((void**)&part, g_part);
    cudaGetSymbolAddress((void**)&invdeg, g_invdeg);
    cudaGetSymbolAddress((void**)&invsqrt, g_invsqrt);
    cudaGetSymbolAddress((void**)&ew, g_ew);
    cudaGetSymbolAddress((void**)&deg, g_deg);
    cudaGetSymbolAddress((void**)&cursor, g_cursor);
    cudaGetSymbolAddress((void**)&rowptr, g_rowptr);
    cudaGetSymbolAddress((void**)&eid, g_eid);
    cudaGetSymbolAddress((void**)&srcs, g_srcs);
    cudaGetSymbolAddress((void**)&bsum, g_bsum);

    cudaFuncSetAttribute(k_step, cudaFuncAttributeMaxDynamicSharedMemorySize, STEP_SMEM);

    k_zero2<<<(NN + 255) / 256, 256>>>(deg, cursor);
    k_deg<<<(EE + 255) / 256, 256>>>(dstI, deg);
    k_degfin<<<(NN + 255) / 256, 256>>>(deg, invdeg, invsqrt);
    k_scan1<<<SCAN_B, 128>>>(deg, rowptr, bsum);
    k_scan2<<<1, 512>>>(bsum);
    k_scan3<<<(NN + 255) / 256, 256>>>(rowptr, bsum);
    k_scatter<<<(EE + 255) / 256, 256>>>(dstI, rowptr, cursor, eid);
    k_sortfill<<<(NN + 127) / 128, 128>>>(rowptr, eid, srcI, invsqrt, srcs, ew);

    k_softmax<<<1, 16>>>(alphas, wmix);
    k_bake<<<28, 256>>>(wmix, Wgcn, Wss, Wsn, Wgin, Wgc1, Wgc2, Wmlp, Wgcnii, wbk);

    k_gemm<<<dim3(MT64, 3), 256>>>(x, 128, stemW, 192, stem, 128);
    bnrun(stem, 192, 0, part, stats);
    k_gemm<<<dim3(MT64, 1), 256>>>(x, 128, preW, 64, x0p, 128);
    bnrun(x0p, 64, 1, part, stats);

    const int aggBlocks = (NN * 32 + 255) / 256;
    for (int ci = 0; ci < 2; ci++) {
        const float* s0 = stem; int k0 = 192;
        const float* s1 = (ci == 0) ? stem : c0;
        int k1 = (ci == 0) ? 192 : 256;
        const float* pW0 = (ci == 0) ? p0W0 : p0W1;
        const float* pW1 = (ci == 0) ? p1W0 : p1W1;
        float* cell = (ci == 0) ? c0 : c1;

        k_gemm<<<dim3(MT64, 1), 256>>>(s0, k0, pW0, 64, ap, k0);
        bnrun(ap, 64, 1, part, stats);
        k_gemm<<<dim3(MT64, 1), 256>>>(s1, k1, pW1, 64, bp, k1);
        bnrun(bp, 64, 1, part, stats);

        const float* sp[5] = {ap, bp, cell, cell + 64, cell + 128};
        const int sl[5] = {64, 64, 256, 256, 256};
        k_agg<<<aggBlocks, 256>>>(sp[0], sl[0], rowptr, srcs, ew, sums, nrms);
        k_agg<<<aggBlocks, 256>>>(sp[1], sl[1], rowptr, srcs, ew, sums + (size_t)NSZ, nrms + (size_t)NSZ);

        int ej0 = 0;
        for (int t = 0; t < 4; t++) {
            const __nv_bfloat16* wb = wbk + (size_t)(ci * 14 + ej0) * 8 * 8192;
            k_step<<<MT64, 128, STEP_SMEM>>>(sp[0], sp[1], sp[2], sp[3], sp[4],
                                             sl[0], sl[1], sl[2], sl[3], sl[4],
                                             sums, nrms, x0p, invdeg, wb, t + 2, cell + t * 64);
            ej0 += t + 2;
            if (t < 3) {
                int ns = t + 2;
                k_agg<<<aggBlocks, 256>>>(sp[ns], sl[ns], rowptr, srcs, ew,
                                          sums + (size_t)ns * NSZ, nrms + (size_t)ns * NSZ);
            }
        }
    }
    k_cls<<<NN, 64>>>(c1, clsW, clsb, out);
}